// round 13
// baseline (speedup 1.0000x reference)
#include <cuda_runtime.h>
#include <cuda_fp16.h>
#include <cstdint>
#include <math.h>

// ---------------------------------------------------------------------------
// ActorMultiHead — fp16 mma.sync (m16n8k16, fp32 accum) + role compaction.
// R13: BK=64 (half the barrier/pipeline events), parallel compaction scan.
//
//   1. compact tokens: role0 -> [0,C0), role1 -> [S1,S1+C1), S1=align128(C0)
//   2. 3 shared layers on M2 rows (~2/3 of tokens), fp16 in / fp32 acc
//   3. head1 ONE launch over [0,M2); per-block weight select at S1 boundary
//   4. head2+logprob gathers via slot map; role2 -> exact 0
// Weights pre-packed fp16 TRANSPOSED [N][K]; activations fp16 [M][K].
// ---------------------------------------------------------------------------

#define M_TOTAL  32768
#define MMAX     (M_TOTAL + 256)
#define BM 128
#define BN 128
#define BK 64
#define TSB 72                       // smem row stride in halfs (144B): banks 4r mod 32
#define TILE_H (128 * TSB)           // 9216 halfs per (A|B) tile
#define STG_H  (2 * TILE_H)          // 18432 halfs per stage
#define SMEM_BYTES (2 * STG_H * 2)   // 73728 B (dynamic, opt-in)

#define K0PAD 192                    // layer-0 K padded to BK multiple

// fp16 transposed weight pack offsets (halfs)
#define W0T_OFF  0                               // [1024][192]
#define W1T_OFF  (1024 * K0PAD)
#define W2T_OFF  (W1T_OFF + 1024 * 1024)
#define HW1T_OFF (W2T_OFF + 1024 * 1024)         // [2][512][1024]
#define WT_TOTAL (HW1T_OFF + 2 * 512 * 1024)

// Scratch (allocation-free __device__ globals)
__device__ __half g_bufA[MMAX * 1024];
__device__ __half g_bufB[MMAX * 1024];
__device__ __half g_xpad[MMAX * K0PAD];
__device__ __half g_z[MMAX * 512];
__device__ __half g_wt[WT_TOTAL];
__device__ int   g_slot[M_TOTAL];
__device__ int   g_cnt0[256], g_cnt1[256];
__device__ int   g_base0[256], g_base1[256];
__device__ int   g_meta[8];   // 1:M2  3:S1  6:C0  7:C1

__device__ __forceinline__ void mma_f16(float d[4], const unsigned a[4], const unsigned b[2]) {
    asm("mma.sync.aligned.m16n8k16.row.col.f32.f16.f16.f32 "
        "{%0,%1,%2,%3}, {%4,%5,%6,%7}, {%8,%9}, {%0,%1,%2,%3};\n"
        : "+f"(d[0]), "+f"(d[1]), "+f"(d[2]), "+f"(d[3])
        : "r"(a[0]), "r"(a[1]), "r"(a[2]), "r"(a[3]), "r"(b[0]), "r"(b[1]));
}

__device__ __forceinline__ void cp16(unsigned s, const void* g) {
    asm volatile("cp.async.cg.shared.global [%0], [%1], 16;\n" :: "r"(s), "l"(g));
}

__device__ __forceinline__ void ldsm_x4(unsigned &r0, unsigned &r1, unsigned &r2,
                                        unsigned &r3, unsigned a) {
    asm volatile("ldmatrix.sync.aligned.m8n8.x4.shared.b16 {%0,%1,%2,%3}, [%4];"
                 : "=r"(r0), "=r"(r1), "=r"(r2), "=r"(r3) : "r"(a));
}

// ---------------------------------------------------------------------------
// Compaction: count -> scan (parallel) -> slot assignment
// ---------------------------------------------------------------------------
__global__ void count_roles(const int* __restrict__ roles)
{
    const int blk = blockIdx.x, tid = threadIdx.x;     // 256 x 128
    const int role = roles[blk * 128 + tid];
    const unsigned m0 = __ballot_sync(0xffffffffu, role == 0);
    const unsigned m1 = __ballot_sync(0xffffffffu, role == 1);
    __shared__ int c0[4], c1[4];
    if ((tid & 31) == 0) { c0[tid >> 5] = __popc(m0); c1[tid >> 5] = __popc(m1); }
    __syncthreads();
    if (tid == 0) {
        g_cnt0[blk] = c0[0] + c0[1] + c0[2] + c0[3];
        g_cnt1[blk] = c1[0] + c1[1] + c1[2] + c1[3];
    }
}

__global__ void scan_roles()        // 256 threads, Hillis-Steele
{
    __shared__ int s0[256], s1[256];
    const int tid = threadIdx.x;
    const int my0 = g_cnt0[tid], my1 = g_cnt1[tid];
    s0[tid] = my0; s1[tid] = my1;
    __syncthreads();
    for (int d = 1; d < 256; d <<= 1) {
        int v0 = (tid >= d) ? s0[tid - d] : 0;
        int v1 = (tid >= d) ? s1[tid - d] : 0;
        __syncthreads();
        s0[tid] += v0; s1[tid] += v1;
        __syncthreads();
    }
    const int C0 = s0[255];
    const int S1 = (C0 + 127) & ~127;
    g_base0[tid] = s0[tid] - my0;              // exclusive prefix
    g_base1[tid] = S1 + s1[tid] - my1;
    if (tid == 255) {
        const int C1 = s1[255];
        const int M2 = S1 + ((C1 + 127) & ~127);
        g_meta[0] = 0;  g_meta[1] = M2;
        g_meta[2] = 0;  g_meta[3] = S1;
        g_meta[4] = S1; g_meta[5] = M2;
        g_meta[6] = C0; g_meta[7] = C1;
    }
}

__global__ void assign_slots(const int* __restrict__ roles)
{
    const int blk = blockIdx.x, tid = threadIdx.x;
    const int t = blk * 128 + tid;
    const int role = roles[t];
    const unsigned lt = (1u << (tid & 31)) - 1u;
    const unsigned m0 = __ballot_sync(0xffffffffu, role == 0);
    const unsigned m1 = __ballot_sync(0xffffffffu, role == 1);
    __shared__ int c0[4], c1[4];
    if ((tid & 31) == 0) { c0[tid >> 5] = __popc(m0); c1[tid >> 5] = __popc(m1); }
    __syncthreads();
    int off0 = 0, off1 = 0;
    for (int w = 0; w < (tid >> 5); w++) { off0 += c0[w]; off1 += c1[w]; }
    int slot = -1;
    if (role == 0)      slot = g_base0[blk] + off0 + __popc(m0 & lt);
    else if (role == 1) slot = g_base1[blk] + off1 + __popc(m1 & lt);
    g_slot[t] = slot;
}

// xp[slot] = fp16(concat(obs, onehot), zero-pad to 192); 8 tokens per block
__global__ void pack_x_compact(const float* __restrict__ obs,
                               const int* __restrict__ roles,
                               __half* __restrict__ xp)
{
    const int k = threadIdx.x;          // 0..191
#pragma unroll
    for (int j = 0; j < 8; j++) {
        const int t = blockIdx.x * 8 + j;
        const int p = g_slot[t];
        if (p < 0) continue;
        float v = 0.f;
        if (k < 128)      v = obs[t * 128 + k];
        else if (k < 130) v = (roles[t] == (k - 128)) ? 1.f : 0.f;
        xp[p * K0PAD + k] = __float2half(v);
    }
}

__global__ void zero_pads(__half* __restrict__ xp)
{
    const int i = blockIdx.x;           // up to 256 pad rows
    const int C0 = g_meta[6], C1 = g_meta[7];
    const int S1 = g_meta[3], M2 = g_meta[1];
    const int p0 = S1 - C0;
    int row;
    if (i < p0) row = C0 + i;
    else if (i - p0 < M2 - (S1 + C1)) row = S1 + C1 + (i - p0);
    else return;
    xp[row * K0PAD + threadIdx.x] = __float2half(0.f);
}

// ---------------------------------------------------------------------------
// Fused weight transpose-pack: dst[n][k] = fp16(src[k][n]), k >= srcK -> 0.
// One launch; blockIdx selects job + tile. grid = 3264 blocks, block (32,8).
// ---------------------------------------------------------------------------
__global__ void transpose_all(const float* __restrict__ W0,
                              const float* __restrict__ W1,
                              const float* __restrict__ W2,
                              const float* __restrict__ hW1,
                              __half* __restrict__ wt)
{
    __shared__ float tile[32][33];
    int bid = blockIdx.x;
    const float* src; int srcK, srcN, dld, kT; __half* dst;
    if (bid < 192)       { src = W0;              srcK = 130;  srcN = 1024; dst = wt + W0T_OFF;              dld = K0PAD; kT = 6;  }
    else if (bid < 1216) { bid -= 192;  src = W1; srcK = 1024; srcN = 1024; dst = wt + W1T_OFF;              dld = 1024;  kT = 32; }
    else if (bid < 2240) { bid -= 1216; src = W2; srcK = 1024; srcN = 1024; dst = wt + W2T_OFF;              dld = 1024;  kT = 32; }
    else if (bid < 2752) { bid -= 2240; src = hW1;             srcK = 1024; srcN = 512; dst = wt + HW1T_OFF;             dld = 1024; kT = 32; }
    else                 { bid -= 2752; src = hW1 + 1024*512;  srcK = 1024; srcN = 512; dst = wt + HW1T_OFF + 512*1024; dld = 1024; kT = 32; }
    const int k0 = (bid % kT) * 32, n0 = (bid / kT) * 32;
    for (int i = threadIdx.y; i < 32; i += 8) {
        int k = k0 + i;
        tile[i][threadIdx.x] = (k < srcK) ? src[(size_t)k * srcN + n0 + threadIdx.x] : 0.f;
    }
    __syncthreads();
    for (int i = threadIdx.y; i < 32; i += 8)
        dst[(size_t)(n0 + i) * dld + k0 + threadIdx.x] =
            __float2half(tile[threadIdx.x][i]);
}

// ---------------------------------------------------------------------------
// fp16 GEMM: C[rows,N] = fp16(relu(A @ Bt^T + bias)); rows=[0, meta[1]).
// SPLIT=1: blocks with blockM >= meta[3] use (Bt1, bias1).
// 256 threads, 8 warps (4x2), warp tile 32x64, BK=64 double-buffered cp.async,
// ldmatrix.x4 fragment loads.
// ---------------------------------------------------------------------------
template <int SPLIT>
__global__ void __launch_bounds__(256, 2)
gemm_f16(const __half* __restrict__ A, int lda,
         const __half* __restrict__ Bt0, const __half* __restrict__ Bt1, int ldb,
         const float* __restrict__ bias0, const float* __restrict__ bias1,
         __half* __restrict__ C, int ldc, int K,
         const int* __restrict__ meta)
{
    const int blockM = blockIdx.y * BM;
    if (blockM >= meta[1]) return;
    const int blockN = blockIdx.x * BN;

    const __half* Bt = Bt0;
    const float* bias = bias0;
    if (SPLIT && blockM >= meta[3]) { Bt = Bt1; bias = bias1; }

    extern __shared__ __half smem[];     // 2 * STG_H halfs = 73728 B
    const unsigned smemB = (unsigned)__cvta_generic_to_shared(smem);

    const int tid  = threadIdx.x;
    const int lane = tid & 31;
    const int warp = tid >> 5;
    const int wm = warp >> 1;            // 4 warps along M (32 rows each)
    const int wn = warp & 1;             // 2 warps along N (64 cols each)

    // staging: thread handles row tid>>1, 64 B = 4 x 16B chunks per matrix
    const int sRow = tid >> 1, sOff = (tid & 1) * 32;   // halfs
    const __half* aG0 = A  + (size_t)(blockM + sRow) * lda + sOff;
    const __half* bG0 = Bt + (size_t)(blockN + sRow) * ldb + sOff;
    const unsigned aS0 = smemB + (unsigned)(sRow * TSB + sOff) * 2;
    const unsigned bS0 = smemB + (unsigned)(TILE_H + sRow * TSB + sOff) * 2;

    auto stage = [&](int kt) {
        const unsigned so = (unsigned)(kt & 1) * (STG_H * 2);
        const __half* ag = aG0 + kt * BK;
        const __half* bg = bG0 + kt * BK;
#pragma unroll
        for (int i = 0; i < 4; i++) cp16(aS0 + so + i * 16, ag + i * 8);
#pragma unroll
        for (int i = 0; i < 4; i++) cp16(bS0 + so + i * 16, bg + i * 8);
        asm volatile("cp.async.commit_group;\n");
    };

    // ldmatrix per-lane source addresses (bytes):
    // A x4: row = wm*32 + mi*16 + (lane&15), col halfs = ks*16 + ((lane>>4)<<3)
    // B x4: n   = wn*64 + np*16 + (lane&7) + ((lane>>4)<<3),
    //       col halfs = ks*16 + (((lane>>3)&1)<<3)
    const unsigned aLd = smemB +
        (unsigned)(((wm * 32 + (lane & 15)) * TSB + ((lane >> 4) << 3)) * 2);
    const unsigned bLd = smemB +
        (unsigned)((TILE_H + (wn * 64 + (lane & 7) + ((lane >> 4) << 3)) * TSB
                    + (((lane >> 3) & 1) << 3)) * 2);

    float acc[2][8][4];
#pragma unroll
    for (int mi = 0; mi < 2; mi++)
#pragma unroll
        for (int ni = 0; ni < 8; ni++)
#pragma unroll
            for (int c = 0; c < 4; c++) acc[mi][ni][c] = 0.f;

    const int T = K >> 6;
    stage(0);

    for (int kt = 0; kt < T; kt++) {
        if (kt + 1 < T) {
            stage(kt + 1);
            asm volatile("cp.async.wait_group 1;\n" ::: "memory");
        } else {
            asm volatile("cp.async.wait_group 0;\n" ::: "memory");
        }
        __syncthreads();

        const unsigned so = (unsigned)(kt & 1) * (STG_H * 2);

#pragma unroll
        for (int ks = 0; ks < 4; ks++) {               // four k16 steps per BK=64
            const unsigned kb = so + (unsigned)(ks * 32);   // 16 halfs = 32 B
            unsigned a[2][4], b[8][2];
            ldsm_x4(a[0][0], a[0][1], a[0][2], a[0][3], aLd + kb);
            ldsm_x4(a[1][0], a[1][1], a[1][2], a[1][3], aLd + kb + 16 * TSB * 2);
#pragma unroll
            for (int np = 0; np < 4; np++)
                ldsm_x4(b[2*np][0], b[2*np][1], b[2*np+1][0], b[2*np+1][1],
                        bLd + kb + (unsigned)(np * 16 * TSB * 2));
#pragma unroll
            for (int mi = 0; mi < 2; mi++)
#pragma unroll
                for (int ni = 0; ni < 8; ni++)
                    mma_f16(acc[mi][ni], a[mi], b[ni]);
        }
        __syncthreads();
    }

    // epilogue: bias + relu -> fp16 store (half2)
#pragma unroll
    for (int ni = 0; ni < 8; ni++) {
        const int col = blockN + wn * 64 + ni * 8 + 2 * (lane & 3);
        const float bb0 = bias[col];
        const float bb1 = bias[col + 1];
#pragma unroll
        for (int mi = 0; mi < 2; mi++) {
            const int row = blockM + wm * 32 + mi * 16 + (lane >> 2);
            float v0 = fmaxf(acc[mi][ni][0] + bb0, 0.f);
            float v1 = fmaxf(acc[mi][ni][1] + bb1, 0.f);
            float v2 = fmaxf(acc[mi][ni][2] + bb0, 0.f);
            float v3 = fmaxf(acc[mi][ni][3] + bb1, 0.f);
            *(__half2*)&C[(size_t)row * ldc + col]       = __floats2half2_rn(v0, v1);
            *(__half2*)&C[(size_t)(row + 8) * ldc + col] = __floats2half2_rn(v2, v3);
        }
    }
}

// ---------------------------------------------------------------------------
// Head layer 2 + tanh + Gaussian log prob; gathers fp16 Z via slot map.
// ---------------------------------------------------------------------------
__global__ void __launch_bounds__(256)
head2_logprob_kernel(const __half* __restrict__ Z,      // [M2,512] compact fp16
                     const int*   __restrict__ role_ids,
                     const float* __restrict__ actions,
                     const float* __restrict__ hW2,     // [2*512*8]
                     const float* __restrict__ hb2,
                     const float* __restrict__ logstd,
                     float* __restrict__ out)
{
    __shared__ float sW[2 * 8 * 512];  // [r][k][m]
    __shared__ float sb[16];
    __shared__ float sls[16];

    const int tid = threadIdx.x;
    for (int idx = tid; idx < 8192; idx += 256) {
        int r = idx >> 12, rem = idx & 4095, m = rem >> 3, k = rem & 7;
        sW[r * 4096 + k * 512 + m] = hW2[idx];
    }
    if (tid < 16) { sb[tid] = hb2[tid]; sls[tid] = logstd[tid]; }
    __syncthreads();

    const int warp = tid >> 5, lane = tid & 31;
    const int t = blockIdx.x * 8 + warp;

    const int role = role_ids[t];
    if (role >= 2) { if (lane == 0) out[t] = 0.f; return; }
    const int p = g_slot[t];

    const __half2* z2 = (const __half2*)(Z + (size_t)p * 512);
    const float* w = sW + role * 4096;

    float s[8];
#pragma unroll
    for (int k = 0; k < 8; k++) s[k] = 0.f;
#pragma unroll
    for (int j = 0; j < 8; j++) {
        const int i2 = lane + j * 32;            // half2 index, 256 total
        const float2 zf = __half22float2(z2[i2]);
        const int m = i2 * 2;
#pragma unroll
        for (int k = 0; k < 8; k++)
            s[k] += zf.x * w[k * 512 + m] + zf.y * w[k * 512 + m + 1];
    }
#pragma unroll
    for (int k = 0; k < 8; k++)
#pragma unroll
        for (int off = 16; off; off >>= 1)
            s[k] += __shfl_xor_sync(0xffffffffu, s[k], off);

    if (lane == 0) {
        float lp = 0.f;
#pragma unroll
        for (int k = 0; k < 8; k++) {
            float mean = tanhf(s[k] + sb[role * 8 + k]);
            float ls = sls[role * 8 + k];
            float d = (actions[t * 8 + k] - mean) * expf(-ls);
            lp += -0.5f * d * d - ls - 0.91893853320467274178f;
        }
        out[t] = lp;
    }
}

extern "C" void kernel_launch(void* const* d_in, const int* in_sizes, int n_in,
                              void* d_out, int out_size)
{
    const float* obs      = (const float*)d_in[0];
    const int*   role_ids = (const int*)  d_in[1];
    const float* actions  = (const float*)d_in[2];
    const float* W0  = (const float*)d_in[3];
    const float* b0  = (const float*)d_in[4];
    const float* W1  = (const float*)d_in[5];
    const float* b1  = (const float*)d_in[6];
    const float* W2  = (const float*)d_in[7];
    const float* b2  = (const float*)d_in[8];
    const float* hW1 = (const float*)d_in[9];
    const float* hb1 = (const float*)d_in[10];  // [2,512]
    const float* hW2 = (const float*)d_in[11];
    const float* hb2 = (const float*)d_in[12];
    const float* lsd = (const float*)d_in[13];
    float* out = (float*)d_out;

    __half *bufA, *bufB, *xpad, *zb, *wt;
    int *meta;
    cudaGetSymbolAddress((void**)&bufA, g_bufA);
    cudaGetSymbolAddress((void**)&bufB, g_bufB);
    cudaGetSymbolAddress((void**)&xpad, g_xpad);
    cudaGetSymbolAddress((void**)&zb,   g_z);
    cudaGetSymbolAddress((void**)&wt,   g_wt);
    cudaGetSymbolAddress((void**)&meta, g_meta);

    cudaFuncSetAttribute(gemm_f16<0>, cudaFuncAttributeMaxDynamicSharedMemorySize, SMEM_BYTES);
    cudaFuncSetAttribute(gemm_f16<1>, cudaFuncAttributeMaxDynamicSharedMemorySize, SMEM_BYTES);

    // compaction + packs
    count_roles<<<256, 128>>>(role_ids);
    scan_roles<<<1, 256>>>();
    assign_slots<<<256, 128>>>(role_ids);
    pack_x_compact<<<M_TOTAL / 8, K0PAD>>>(obs, role_ids, xpad);
    zero_pads<<<256, K0PAD>>>(xpad);
    transpose_all<<<3264, dim3(32, 8)>>>(W0, W1, W2, hW1, wt);

    const int GY = MMAX / BM;             // 258, blocks early-exit past M2
    dim3 block(256);
    dim3 gridMain(8, GY);                 // N=1024
    dim3 gridHead(4, GY);                 // N=512

    // shared layers on compacted rows [0, M2)
    gemm_f16<0><<<gridMain, block, SMEM_BYTES>>>(xpad, K0PAD, wt + W0T_OFF, wt + W0T_OFF, K0PAD, b0, b0, bufA, 1024, K0PAD, meta);
    gemm_f16<0><<<gridMain, block, SMEM_BYTES>>>(bufA, 1024,  wt + W1T_OFF, wt + W1T_OFF, 1024,  b1, b1, bufB, 1024, 1024,  meta);
    gemm_f16<0><<<gridMain, block, SMEM_BYTES>>>(bufB, 1024,  wt + W2T_OFF, wt + W2T_OFF, 1024,  b2, b2, bufA, 1024, 1024,  meta);
    // head1, single launch: role0 weights below S1, role1 above
    gemm_f16<1><<<gridHead, block, SMEM_BYTES>>>(bufA, 1024,
                                                 wt + HW1T_OFF, wt + HW1T_OFF + 512*1024, 1024,
                                                 hb1, hb1 + 512,
                                                 zb, 512, 1024, meta);
    // head2 + tanh + Gaussian log-prob, gather via slot map
    head2_logprob_kernel<<<M_TOTAL / 8, 256>>>(zb, role_ids, actions,
                                               hW2, hb2, lsd, out);
}

// round 14
// speedup vs baseline: 1.1203x; 1.1203x over previous
#include <cuda_runtime.h>
#include <cuda_fp16.h>
#include <cstdint>
#include <math.h>

// ---------------------------------------------------------------------------
// ActorMultiHead — fp16 mma.sync (m16n8k16, fp32 accum) + role compaction.
// R14: R12 base (best) + 3-stage cp.async ring with ONE syncthreads/k-tile.
//
//   1. compact tokens: role0 -> [0,C0), role1 -> [S1,S1+C1), S1=align128(C0)
//   2. 3 shared layers on M2 rows (~2/3 of tokens), fp16 in / fp32 acc
//   3. head1 ONE launch over [0,M2); per-block weight select at S1 boundary
//   4. head2+logprob gathers via slot map; role2 -> exact 0
// Weights pre-packed fp16 TRANSPOSED [N][K]; activations fp16 [M][K].
// ---------------------------------------------------------------------------

#define M_TOTAL  32768
#define MMAX     (M_TOTAL + 256)
#define BM 128
#define BN 128
#define BK 32
#define TS 40                        // smem row stride in halfs (80B): conflict-free
#define TILE_H (128 * TS)            // 5120 halfs per (A|B) tile
#define STG_H  (2 * TILE_H)          // 10240 halfs per stage
#define NSTAGE 3
#define SMEM_BYTES (NSTAGE * STG_H * 2)   // 61440 B dynamic

// fp16 transposed weight pack offsets (halfs)
#define W0T_OFF  0                               // [1024][160]
#define W1T_OFF  (1024 * 160)
#define W2T_OFF  (W1T_OFF + 1024 * 1024)
#define HW1T_OFF (W2T_OFF + 1024 * 1024)         // [2][512][1024]
#define WT_TOTAL (HW1T_OFF + 2 * 512 * 1024)

// Scratch (allocation-free __device__ globals)
__device__ __half g_bufA[MMAX * 1024];
__device__ __half g_bufB[MMAX * 1024];
__device__ __half g_xpad[MMAX * 160];
__device__ __half g_z[MMAX * 512];
__device__ __half g_wt[WT_TOTAL];
__device__ int   g_slot[M_TOTAL];
__device__ int   g_cnt0[256], g_cnt1[256];
__device__ int   g_base0[256], g_base1[256];
__device__ int   g_meta[8];   // 1:M2  3:S1  6:C0  7:C1

__device__ __forceinline__ void mma_f16(float d[4], const unsigned a[4], const unsigned b[2]) {
    asm("mma.sync.aligned.m16n8k16.row.col.f32.f16.f16.f32 "
        "{%0,%1,%2,%3}, {%4,%5,%6,%7}, {%8,%9}, {%0,%1,%2,%3};\n"
        : "+f"(d[0]), "+f"(d[1]), "+f"(d[2]), "+f"(d[3])
        : "r"(a[0]), "r"(a[1]), "r"(a[2]), "r"(a[3]), "r"(b[0]), "r"(b[1]));
}

__device__ __forceinline__ void cp16(unsigned s, const void* g) {
    asm volatile("cp.async.cg.shared.global [%0], [%1], 16;\n" :: "r"(s), "l"(g));
}

__device__ __forceinline__ void ldsm_x4(unsigned &r0, unsigned &r1, unsigned &r2,
                                        unsigned &r3, unsigned a) {
    asm volatile("ldmatrix.sync.aligned.m8n8.x4.shared.b16 {%0,%1,%2,%3}, [%4];"
                 : "=r"(r0), "=r"(r1), "=r"(r2), "=r"(r3) : "r"(a));
}

// ---------------------------------------------------------------------------
// Compaction: count -> scan (parallel) -> slot assignment
// ---------------------------------------------------------------------------
__global__ void count_roles(const int* __restrict__ roles)
{
    const int blk = blockIdx.x, tid = threadIdx.x;     // 256 x 128
    const int role = roles[blk * 128 + tid];
    const unsigned m0 = __ballot_sync(0xffffffffu, role == 0);
    const unsigned m1 = __ballot_sync(0xffffffffu, role == 1);
    __shared__ int c0[4], c1[4];
    if ((tid & 31) == 0) { c0[tid >> 5] = __popc(m0); c1[tid >> 5] = __popc(m1); }
    __syncthreads();
    if (tid == 0) {
        g_cnt0[blk] = c0[0] + c0[1] + c0[2] + c0[3];
        g_cnt1[blk] = c1[0] + c1[1] + c1[2] + c1[3];
    }
}

__global__ void scan_roles()        // 256 threads, Hillis-Steele
{
    __shared__ int s0[256], s1[256];
    const int tid = threadIdx.x;
    const int my0 = g_cnt0[tid], my1 = g_cnt1[tid];
    s0[tid] = my0; s1[tid] = my1;
    __syncthreads();
    for (int d = 1; d < 256; d <<= 1) {
        int v0 = (tid >= d) ? s0[tid - d] : 0;
        int v1 = (tid >= d) ? s1[tid - d] : 0;
        __syncthreads();
        s0[tid] += v0; s1[tid] += v1;
        __syncthreads();
    }
    const int C0 = s0[255];
    const int S1 = (C0 + 127) & ~127;
    g_base0[tid] = s0[tid] - my0;              // exclusive prefix
    g_base1[tid] = S1 + s1[tid] - my1;
    if (tid == 255) {
        const int C1 = s1[255];
        const int M2 = S1 + ((C1 + 127) & ~127);
        g_meta[0] = 0;  g_meta[1] = M2;
        g_meta[2] = 0;  g_meta[3] = S1;
        g_meta[4] = S1; g_meta[5] = M2;
        g_meta[6] = C0; g_meta[7] = C1;
    }
}

__global__ void assign_slots(const int* __restrict__ roles)
{
    const int blk = blockIdx.x, tid = threadIdx.x;
    const int t = blk * 128 + tid;
    const int role = roles[t];
    const unsigned lt = (1u << (tid & 31)) - 1u;
    const unsigned m0 = __ballot_sync(0xffffffffu, role == 0);
    const unsigned m1 = __ballot_sync(0xffffffffu, role == 1);
    __shared__ int c0[4], c1[4];
    if ((tid & 31) == 0) { c0[tid >> 5] = __popc(m0); c1[tid >> 5] = __popc(m1); }
    __syncthreads();
    int off0 = 0, off1 = 0;
    for (int w = 0; w < (tid >> 5); w++) { off0 += c0[w]; off1 += c1[w]; }
    int slot = -1;
    if (role == 0)      slot = g_base0[blk] + off0 + __popc(m0 & lt);
    else if (role == 1) slot = g_base1[blk] + off1 + __popc(m1 & lt);
    g_slot[t] = slot;
}

// xp[slot] = fp16(concat(obs, onehot), zero-pad to 160); 8 tokens per block
__global__ void pack_x_compact(const float* __restrict__ obs,
                               const int* __restrict__ roles,
                               __half* __restrict__ xp)
{
    const int k = threadIdx.x;          // 0..159
#pragma unroll
    for (int j = 0; j < 8; j++) {
        const int t = blockIdx.x * 8 + j;
        const int p = g_slot[t];
        if (p < 0) continue;
        float v = 0.f;
        if (k < 128)      v = obs[t * 128 + k];
        else if (k < 130) v = (roles[t] == (k - 128)) ? 1.f : 0.f;
        xp[p * 160 + k] = __float2half(v);
    }
}

__global__ void zero_pads(__half* __restrict__ xp)
{
    const int i = blockIdx.x;           // up to 256 pad rows
    const int C0 = g_meta[6], C1 = g_meta[7];
    const int S1 = g_meta[3], M2 = g_meta[1];
    const int p0 = S1 - C0;
    int row;
    if (i < p0) row = C0 + i;
    else if (i - p0 < M2 - (S1 + C1)) row = S1 + C1 + (i - p0);
    else return;
    xp[row * 160 + threadIdx.x] = __float2half(0.f);
}

// ---------------------------------------------------------------------------
// Fused weight transpose-pack: dst[n][k] = fp16(src[k][n]), k >= srcK -> 0.
// One launch; blockIdx selects job + tile. grid = 3232 blocks, block (32,8).
// ---------------------------------------------------------------------------
__global__ void transpose_all(const float* __restrict__ W0,
                              const float* __restrict__ W1,
                              const float* __restrict__ W2,
                              const float* __restrict__ hW1,
                              __half* __restrict__ wt)
{
    __shared__ float tile[32][33];
    int bid = blockIdx.x;
    const float* src; int srcK, srcN, dld, kT; __half* dst;
    if (bid < 160)       { src = W0;              srcK = 130;  srcN = 1024; dst = wt + W0T_OFF;              dld = 160;  kT = 5;  }
    else if (bid < 1184) { bid -= 160;  src = W1; srcK = 1024; srcN = 1024; dst = wt + W1T_OFF;              dld = 1024; kT = 32; }
    else if (bid < 2208) { bid -= 1184; src = W2; srcK = 1024; srcN = 1024; dst = wt + W2T_OFF;              dld = 1024; kT = 32; }
    else if (bid < 2720) { bid -= 2208; src = hW1;             srcK = 1024; srcN = 512; dst = wt + HW1T_OFF;             dld = 1024; kT = 32; }
    else                 { bid -= 2720; src = hW1 + 1024*512;  srcK = 1024; srcN = 512; dst = wt + HW1T_OFF + 512*1024; dld = 1024; kT = 32; }
    const int k0 = (bid % kT) * 32, n0 = (bid / kT) * 32;
    for (int i = threadIdx.y; i < 32; i += 8) {
        int k = k0 + i;
        tile[i][threadIdx.x] = (k < srcK) ? src[(size_t)k * srcN + n0 + threadIdx.x] : 0.f;
    }
    __syncthreads();
    for (int i = threadIdx.y; i < 32; i += 8)
        dst[(size_t)(n0 + i) * dld + k0 + threadIdx.x] =
            __float2half(tile[threadIdx.x][i]);
}

// ---------------------------------------------------------------------------
// fp16 GEMM: C[rows,N] = fp16(relu(A @ Bt^T + bias)); rows=[0, meta[1]).
// SPLIT=1: blocks with blockM >= meta[3] use (Bt1, bias1).
// 256 threads, 8 warps (4x2), warp tile 32x64, 3-stage cp.async ring with
// a single __syncthreads per k-tile, ldmatrix.x4 fragment loads.
// ---------------------------------------------------------------------------
template <int SPLIT>
__global__ void __launch_bounds__(256, 2)
gemm_f16(const __half* __restrict__ A, int lda,
         const __half* __restrict__ Bt0, const __half* __restrict__ Bt1, int ldb,
         const float* __restrict__ bias0, const float* __restrict__ bias1,
         __half* __restrict__ C, int ldc, int K,
         const int* __restrict__ meta)
{
    const int blockM = blockIdx.y * BM;
    if (blockM >= meta[1]) return;
    const int blockN = blockIdx.x * BN;

    const __half* Bt = Bt0;
    const float* bias = bias0;
    if (SPLIT && blockM >= meta[3]) { Bt = Bt1; bias = bias1; }

    extern __shared__ __half smem[];     // NSTAGE * STG_H halfs = 61440 B
    const unsigned smemB = (unsigned)__cvta_generic_to_shared(smem);

    const int tid  = threadIdx.x;
    const int lane = tid & 31;
    const int warp = tid >> 5;
    const int wm = warp >> 1;            // 4 warps along M (32 rows each)
    const int wn = warp & 1;             // 2 warps along N (64 cols each)

    // staging: thread handles row tid>>1 of A and of B, 2 x 16B chunks each
    const int sRow = tid >> 1, sOff = (tid & 1) * 16;   // halfs
    const __half* aG0 = A  + (size_t)(blockM + sRow) * lda + sOff;
    const __half* bG0 = Bt + (size_t)(blockN + sRow) * ldb + sOff;
    const unsigned aS0 = smemB + (unsigned)(sRow * TS + sOff) * 2;
    const unsigned bS0 = smemB + (unsigned)(TILE_H + sRow * TS + sOff) * 2;

    auto stage = [&](int kt) {
        const unsigned so = (unsigned)(kt % NSTAGE) * (STG_H * 2);
        const __half* ag = aG0 + kt * BK;
        const __half* bg = bG0 + kt * BK;
        cp16(aS0 + so,      ag);
        cp16(aS0 + so + 16, ag + 8);
        cp16(bS0 + so,      bg);
        cp16(bS0 + so + 16, bg + 8);
        asm volatile("cp.async.commit_group;\n");
    };

    // ldmatrix per-lane source addresses (bytes):
    // A x4: row = wm*32 + mi*16 + (lane&15), col halfs = ks*16 + ((lane>>4)<<3)
    // B x4: n   = wn*64 + np*16 + (lane&7) + ((lane>>4)<<3),
    //       col halfs = ks*16 + (((lane>>3)&1)<<3)
    const unsigned aLd = smemB +
        (unsigned)(((wm * 32 + (lane & 15)) * TS + ((lane >> 4) << 3)) * 2);
    const unsigned bLd = smemB +
        (unsigned)((TILE_H + (wn * 64 + (lane & 7) + ((lane >> 4) << 3)) * TS
                    + (((lane >> 3) & 1) << 3)) * 2);

    float acc[2][8][4];
#pragma unroll
    for (int mi = 0; mi < 2; mi++)
#pragma unroll
        for (int ni = 0; ni < 8; ni++)
#pragma unroll
            for (int c = 0; c < 4; c++) acc[mi][ni][c] = 0.f;

    const int T = K >> 5;               // >= 5 for all layers
    stage(0);
    stage(1);

    for (int kt = 0; kt < T; kt++) {
        // make group kt resident (allow 1 newer group in flight)
        if (kt + 1 < T) asm volatile("cp.async.wait_group 1;\n" ::: "memory");
        else            asm volatile("cp.async.wait_group 0;\n" ::: "memory");
        __syncthreads();   // single barrier: publishes buf kt%3 to all warps AND
                           // proves all warps finished reading buf (kt+2)%3
                           // (last consumed at iteration kt-1) before restaging
        if (kt + 2 < T) stage(kt + 2);

        const unsigned so = (unsigned)(kt % NSTAGE) * (STG_H * 2);

#pragma unroll
        for (int ks = 0; ks < 2; ks++) {               // two k16 steps per BK=32
            const unsigned kb = so + (unsigned)(ks * 32);   // 16 halfs = 32 B
            unsigned a[2][4], b[8][2];
            ldsm_x4(a[0][0], a[0][1], a[0][2], a[0][3], aLd + kb);
            ldsm_x4(a[1][0], a[1][1], a[1][2], a[1][3], aLd + kb + 16 * TS * 2);
#pragma unroll
            for (int np = 0; np < 4; np++)
                ldsm_x4(b[2*np][0], b[2*np][1], b[2*np+1][0], b[2*np+1][1],
                        bLd + kb + (unsigned)(np * 16 * TS * 2));
#pragma unroll
            for (int mi = 0; mi < 2; mi++)
#pragma unroll
                for (int ni = 0; ni < 8; ni++)
                    mma_f16(acc[mi][ni], a[mi], b[ni]);
        }
    }

    // epilogue: bias + relu -> fp16 store (half2)
#pragma unroll
    for (int ni = 0; ni < 8; ni++) {
        const int col = blockN + wn * 64 + ni * 8 + 2 * (lane & 3);
        const float bb0 = bias[col];
        const float bb1 = bias[col + 1];
#pragma unroll
        for (int mi = 0; mi < 2; mi++) {
            const int row = blockM + wm * 32 + mi * 16 + (lane >> 2);
            float v0 = fmaxf(acc[mi][ni][0] + bb0, 0.f);
            float v1 = fmaxf(acc[mi][ni][1] + bb1, 0.f);
            float v2 = fmaxf(acc[mi][ni][2] + bb0, 0.f);
            float v3 = fmaxf(acc[mi][ni][3] + bb1, 0.f);
            *(__half2*)&C[(size_t)row * ldc + col]       = __floats2half2_rn(v0, v1);
            *(__half2*)&C[(size_t)(row + 8) * ldc + col] = __floats2half2_rn(v2, v3);
        }
    }
}

// ---------------------------------------------------------------------------
// Head layer 2 + tanh + Gaussian log prob; gathers fp16 Z via slot map.
// ---------------------------------------------------------------------------
__global__ void __launch_bounds__(256)
head2_logprob_kernel(const __half* __restrict__ Z,      // [M2,512] compact fp16
                     const int*   __restrict__ role_ids,
                     const float* __restrict__ actions,
                     const float* __restrict__ hW2,     // [2*512*8]
                     const float* __restrict__ hb2,
                     const float* __restrict__ logstd,
                     float* __restrict__ out)
{
    __shared__ float sW[2 * 8 * 512];  // [r][k][m]
    __shared__ float sb[16];
    __shared__ float sls[16];

    const int tid = threadIdx.x;
    for (int idx = tid; idx < 8192; idx += 256) {
        int r = idx >> 12, rem = idx & 4095, m = rem >> 3, k = rem & 7;
        sW[r * 4096 + k * 512 + m] = hW2[idx];
    }
    if (tid < 16) { sb[tid] = hb2[tid]; sls[tid] = logstd[tid]; }
    __syncthreads();

    const int warp = tid >> 5, lane = tid & 31;
    const int t = blockIdx.x * 8 + warp;

    const int role = role_ids[t];
    if (role >= 2) { if (lane == 0) out[t] = 0.f; return; }
    const int p = g_slot[t];

    const __half2* z2 = (const __half2*)(Z + (size_t)p * 512);
    const float* w = sW + role * 4096;

    float s[8];
#pragma unroll
    for (int k = 0; k < 8; k++) s[k] = 0.f;
#pragma unroll
    for (int j = 0; j < 8; j++) {
        const int i2 = lane + j * 32;            // half2 index, 256 total
        const float2 zf = __half22float2(z2[i2]);
        const int m = i2 * 2;
#pragma unroll
        for (int k = 0; k < 8; k++)
            s[k] += zf.x * w[k * 512 + m] + zf.y * w[k * 512 + m + 1];
    }
#pragma unroll
    for (int k = 0; k < 8; k++)
#pragma unroll
        for (int off = 16; off; off >>= 1)
            s[k] += __shfl_xor_sync(0xffffffffu, s[k], off);

    if (lane == 0) {
        float lp = 0.f;
#pragma unroll
        for (int k = 0; k < 8; k++) {
            float mean = tanhf(s[k] + sb[role * 8 + k]);
            float ls = sls[role * 8 + k];
            float d = (actions[t * 8 + k] - mean) * expf(-ls);
            lp += -0.5f * d * d - ls - 0.91893853320467274178f;
        }
        out[t] = lp;
    }
}

extern "C" void kernel_launch(void* const* d_in, const int* in_sizes, int n_in,
                              void* d_out, int out_size)
{
    const float* obs      = (const float*)d_in[0];
    const int*   role_ids = (const int*)  d_in[1];
    const float* actions  = (const float*)d_in[2];
    const float* W0  = (const float*)d_in[3];
    const float* b0  = (const float*)d_in[4];
    const float* W1  = (const float*)d_in[5];
    const float* b1  = (const float*)d_in[6];
    const float* W2  = (const float*)d_in[7];
    const float* b2  = (const float*)d_in[8];
    const float* hW1 = (const float*)d_in[9];
    const float* hb1 = (const float*)d_in[10];  // [2,512]
    const float* hW2 = (const float*)d_in[11];
    const float* hb2 = (const float*)d_in[12];
    const float* lsd = (const float*)d_in[13];
    float* out = (float*)d_out;

    __half *bufA, *bufB, *xpad, *zb, *wt;
    int *meta;
    cudaGetSymbolAddress((void**)&bufA, g_bufA);
    cudaGetSymbolAddress((void**)&bufB, g_bufB);
    cudaGetSymbolAddress((void**)&xpad, g_xpad);
    cudaGetSymbolAddress((void**)&zb,   g_z);
    cudaGetSymbolAddress((void**)&wt,   g_wt);
    cudaGetSymbolAddress((void**)&meta, g_meta);

    cudaFuncSetAttribute(gemm_f16<0>, cudaFuncAttributeMaxDynamicSharedMemorySize, SMEM_BYTES);
    cudaFuncSetAttribute(gemm_f16<1>, cudaFuncAttributeMaxDynamicSharedMemorySize, SMEM_BYTES);

    // compaction + packs
    count_roles<<<256, 128>>>(role_ids);
    scan_roles<<<1, 256>>>();
    assign_slots<<<256, 128>>>(role_ids);
    pack_x_compact<<<M_TOTAL / 8, 160>>>(obs, role_ids, xpad);
    zero_pads<<<256, 160>>>(xpad);
    transpose_all<<<3232, dim3(32, 8)>>>(W0, W1, W2, hW1, wt);

    const int GY = MMAX / BM;             // 258, blocks early-exit past M2
    dim3 block(256);
    dim3 gridMain(8, GY);                 // N=1024
    dim3 gridHead(4, GY);                 // N=512

    // shared layers on compacted rows [0, M2)
    gemm_f16<0><<<gridMain, block, SMEM_BYTES>>>(xpad, 160,  wt + W0T_OFF, wt + W0T_OFF, 160,  b0, b0, bufA, 1024, 160,  meta);
    gemm_f16<0><<<gridMain, block, SMEM_BYTES>>>(bufA, 1024, wt + W1T_OFF, wt + W1T_OFF, 1024, b1, b1, bufB, 1024, 1024, meta);
    gemm_f16<0><<<gridMain, block, SMEM_BYTES>>>(bufB, 1024, wt + W2T_OFF, wt + W2T_OFF, 1024, b2, b2, bufA, 1024, 1024, meta);
    // head1, single launch: role0 weights below S1, role1 above
    gemm_f16<1><<<gridHead, block, SMEM_BYTES>>>(bufA, 1024,
                                                 wt + HW1T_OFF, wt + HW1T_OFF + 512*1024, 1024,
                                                 hb1, hb1 + 512,
                                                 zb, 512, 1024, meta);
    // head2 + tanh + Gaussian log-prob, gather via slot map
    head2_logprob_kernel<<<M_TOTAL / 8, 256>>>(zb, role_ids, actions,
                                               hW2, hb2, lsd, out);
}

// round 15
// speedup vs baseline: 1.1290x; 1.0078x over previous
#include <cuda_runtime.h>
#include <cuda_fp16.h>
#include <cstdint>
#include <math.h>

// ---------------------------------------------------------------------------
// ActorMultiHead — fp16 mma.sync (m16n8k16, fp32 accum) + role compaction.
// R15: R14 base + 4-stage cp.async ring (prefetch distance 3, wait_group 2),
// one __syncthreads per k-tile.
//
//   1. compact tokens: role0 -> [0,C0), role1 -> [S1,S1+C1), S1=align128(C0)
//   2. 3 shared layers on M2 rows (~2/3 of tokens), fp16 in / fp32 acc
//   3. head1 ONE launch over [0,M2); per-block weight select at S1 boundary
//   4. head2+logprob gathers via slot map; role2 -> exact 0
// Weights pre-packed fp16 TRANSPOSED [N][K]; activations fp16 [M][K].
// ---------------------------------------------------------------------------

#define M_TOTAL  32768
#define MMAX     (M_TOTAL + 256)
#define BM 128
#define BN 128
#define BK 32
#define TS 40                        // smem row stride in halfs (80B): conflict-free
#define TILE_H (128 * TS)            // 5120 halfs per (A|B) tile
#define STG_H  (2 * TILE_H)          // 10240 halfs per stage
#define NSTAGE 4
#define SMEM_BYTES (NSTAGE * STG_H * 2)   // 81920 B dynamic

// fp16 transposed weight pack offsets (halfs)
#define W0T_OFF  0                               // [1024][160]
#define W1T_OFF  (1024 * 160)
#define W2T_OFF  (W1T_OFF + 1024 * 1024)
#define HW1T_OFF (W2T_OFF + 1024 * 1024)         // [2][512][1024]
#define WT_TOTAL (HW1T_OFF + 2 * 512 * 1024)

// Scratch (allocation-free __device__ globals)
__device__ __half g_bufA[MMAX * 1024];
__device__ __half g_bufB[MMAX * 1024];
__device__ __half g_xpad[MMAX * 160];
__device__ __half g_z[MMAX * 512];
__device__ __half g_wt[WT_TOTAL];
__device__ int   g_slot[M_TOTAL];
__device__ int   g_cnt0[256], g_cnt1[256];
__device__ int   g_base0[256], g_base1[256];
__device__ int   g_meta[8];   // 1:M2  3:S1  6:C0  7:C1

__device__ __forceinline__ void mma_f16(float d[4], const unsigned a[4], const unsigned b[2]) {
    asm("mma.sync.aligned.m16n8k16.row.col.f32.f16.f16.f32 "
        "{%0,%1,%2,%3}, {%4,%5,%6,%7}, {%8,%9}, {%0,%1,%2,%3};\n"
        : "+f"(d[0]), "+f"(d[1]), "+f"(d[2]), "+f"(d[3])
        : "r"(a[0]), "r"(a[1]), "r"(a[2]), "r"(a[3]), "r"(b[0]), "r"(b[1]));
}

__device__ __forceinline__ void cp16(unsigned s, const void* g) {
    asm volatile("cp.async.cg.shared.global [%0], [%1], 16;\n" :: "r"(s), "l"(g));
}

__device__ __forceinline__ void ldsm_x4(unsigned &r0, unsigned &r1, unsigned &r2,
                                        unsigned &r3, unsigned a) {
    asm volatile("ldmatrix.sync.aligned.m8n8.x4.shared.b16 {%0,%1,%2,%3}, [%4];"
                 : "=r"(r0), "=r"(r1), "=r"(r2), "=r"(r3) : "r"(a));
}

// ---------------------------------------------------------------------------
// Compaction: count -> scan (parallel) -> slot assignment
// ---------------------------------------------------------------------------
__global__ void count_roles(const int* __restrict__ roles)
{
    const int blk = blockIdx.x, tid = threadIdx.x;     // 256 x 128
    const int role = roles[blk * 128 + tid];
    const unsigned m0 = __ballot_sync(0xffffffffu, role == 0);
    const unsigned m1 = __ballot_sync(0xffffffffu, role == 1);
    __shared__ int c0[4], c1[4];
    if ((tid & 31) == 0) { c0[tid >> 5] = __popc(m0); c1[tid >> 5] = __popc(m1); }
    __syncthreads();
    if (tid == 0) {
        g_cnt0[blk] = c0[0] + c0[1] + c0[2] + c0[3];
        g_cnt1[blk] = c1[0] + c1[1] + c1[2] + c1[3];
    }
}

__global__ void scan_roles()        // 256 threads, Hillis-Steele
{
    __shared__ int s0[256], s1[256];
    const int tid = threadIdx.x;
    const int my0 = g_cnt0[tid], my1 = g_cnt1[tid];
    s0[tid] = my0; s1[tid] = my1;
    __syncthreads();
    for (int d = 1; d < 256; d <<= 1) {
        int v0 = (tid >= d) ? s0[tid - d] : 0;
        int v1 = (tid >= d) ? s1[tid - d] : 0;
        __syncthreads();
        s0[tid] += v0; s1[tid] += v1;
        __syncthreads();
    }
    const int C0 = s0[255];
    const int S1 = (C0 + 127) & ~127;
    g_base0[tid] = s0[tid] - my0;              // exclusive prefix
    g_base1[tid] = S1 + s1[tid] - my1;
    if (tid == 255) {
        const int C1 = s1[255];
        const int M2 = S1 + ((C1 + 127) & ~127);
        g_meta[0] = 0;  g_meta[1] = M2;
        g_meta[2] = 0;  g_meta[3] = S1;
        g_meta[4] = S1; g_meta[5] = M2;
        g_meta[6] = C0; g_meta[7] = C1;
    }
}

__global__ void assign_slots(const int* __restrict__ roles)
{
    const int blk = blockIdx.x, tid = threadIdx.x;
    const int t = blk * 128 + tid;
    const int role = roles[t];
    const unsigned lt = (1u << (tid & 31)) - 1u;
    const unsigned m0 = __ballot_sync(0xffffffffu, role == 0);
    const unsigned m1 = __ballot_sync(0xffffffffu, role == 1);
    __shared__ int c0[4], c1[4];
    if ((tid & 31) == 0) { c0[tid >> 5] = __popc(m0); c1[tid >> 5] = __popc(m1); }
    __syncthreads();
    int off0 = 0, off1 = 0;
    for (int w = 0; w < (tid >> 5); w++) { off0 += c0[w]; off1 += c1[w]; }
    int slot = -1;
    if (role == 0)      slot = g_base0[blk] + off0 + __popc(m0 & lt);
    else if (role == 1) slot = g_base1[blk] + off1 + __popc(m1 & lt);
    g_slot[t] = slot;
}

// xp[slot] = fp16(concat(obs, onehot), zero-pad to 160); 8 tokens per block
__global__ void pack_x_compact(const float* __restrict__ obs,
                               const int* __restrict__ roles,
                               __half* __restrict__ xp)
{
    const int k = threadIdx.x;          // 0..159
#pragma unroll
    for (int j = 0; j < 8; j++) {
        const int t = blockIdx.x * 8 + j;
        const int p = g_slot[t];
        if (p < 0) continue;
        float v = 0.f;
        if (k < 128)      v = obs[t * 128 + k];
        else if (k < 130) v = (roles[t] == (k - 128)) ? 1.f : 0.f;
        xp[p * 160 + k] = __float2half(v);
    }
}

__global__ void zero_pads(__half* __restrict__ xp)
{
    const int i = blockIdx.x;           // up to 256 pad rows
    const int C0 = g_meta[6], C1 = g_meta[7];
    const int S1 = g_meta[3], M2 = g_meta[1];
    const int p0 = S1 - C0;
    int row;
    if (i < p0) row = C0 + i;
    else if (i - p0 < M2 - (S1 + C1)) row = S1 + C1 + (i - p0);
    else return;
    xp[row * 160 + threadIdx.x] = __float2half(0.f);
}

// ---------------------------------------------------------------------------
// Fused weight transpose-pack: dst[n][k] = fp16(src[k][n]), k >= srcK -> 0.
// One launch; blockIdx selects job + tile. grid = 3232 blocks, block (32,8).
// ---------------------------------------------------------------------------
__global__ void transpose_all(const float* __restrict__ W0,
                              const float* __restrict__ W1,
                              const float* __restrict__ W2,
                              const float* __restrict__ hW1,
                              __half* __restrict__ wt)
{
    __shared__ float tile[32][33];
    int bid = blockIdx.x;
    const float* src; int srcK, srcN, dld, kT; __half* dst;
    if (bid < 160)       { src = W0;              srcK = 130;  srcN = 1024; dst = wt + W0T_OFF;              dld = 160;  kT = 5;  }
    else if (bid < 1184) { bid -= 160;  src = W1; srcK = 1024; srcN = 1024; dst = wt + W1T_OFF;              dld = 1024; kT = 32; }
    else if (bid < 2208) { bid -= 1184; src = W2; srcK = 1024; srcN = 1024; dst = wt + W2T_OFF;              dld = 1024; kT = 32; }
    else if (bid < 2720) { bid -= 2208; src = hW1;             srcK = 1024; srcN = 512; dst = wt + HW1T_OFF;             dld = 1024; kT = 32; }
    else                 { bid -= 2720; src = hW1 + 1024*512;  srcK = 1024; srcN = 512; dst = wt + HW1T_OFF + 512*1024; dld = 1024; kT = 32; }
    const int k0 = (bid % kT) * 32, n0 = (bid / kT) * 32;
    for (int i = threadIdx.y; i < 32; i += 8) {
        int k = k0 + i;
        tile[i][threadIdx.x] = (k < srcK) ? src[(size_t)k * srcN + n0 + threadIdx.x] : 0.f;
    }
    __syncthreads();
    for (int i = threadIdx.y; i < 32; i += 8)
        dst[(size_t)(n0 + i) * dld + k0 + threadIdx.x] =
            __float2half(tile[threadIdx.x][i]);
}

// ---------------------------------------------------------------------------
// fp16 GEMM: C[rows,N] = fp16(relu(A @ Bt^T + bias)); rows=[0, meta[1]).
// SPLIT=1: blocks with blockM >= meta[3] use (Bt1, bias1).
// 256 threads, 8 warps (4x2), warp tile 32x64, 4-stage cp.async ring with
// a single __syncthreads per k-tile, ldmatrix.x4 fragment loads.
// ---------------------------------------------------------------------------
template <int SPLIT>
__global__ void __launch_bounds__(256, 2)
gemm_f16(const __half* __restrict__ A, int lda,
         const __half* __restrict__ Bt0, const __half* __restrict__ Bt1, int ldb,
         const float* __restrict__ bias0, const float* __restrict__ bias1,
         __half* __restrict__ C, int ldc, int K,
         const int* __restrict__ meta)
{
    const int blockM = blockIdx.y * BM;
    if (blockM >= meta[1]) return;
    const int blockN = blockIdx.x * BN;

    const __half* Bt = Bt0;
    const float* bias = bias0;
    if (SPLIT && blockM >= meta[3]) { Bt = Bt1; bias = bias1; }

    extern __shared__ __half smem[];     // NSTAGE * STG_H halfs = 81920 B
    const unsigned smemB = (unsigned)__cvta_generic_to_shared(smem);

    const int tid  = threadIdx.x;
    const int lane = tid & 31;
    const int warp = tid >> 5;
    const int wm = warp >> 1;            // 4 warps along M (32 rows each)
    const int wn = warp & 1;             // 2 warps along N (64 cols each)

    // staging: thread handles row tid>>1 of A and of B, 2 x 16B chunks each
    const int sRow = tid >> 1, sOff = (tid & 1) * 16;   // halfs
    const __half* aG0 = A  + (size_t)(blockM + sRow) * lda + sOff;
    const __half* bG0 = Bt + (size_t)(blockN + sRow) * ldb + sOff;
    const unsigned aS0 = smemB + (unsigned)(sRow * TS + sOff) * 2;
    const unsigned bS0 = smemB + (unsigned)(TILE_H + sRow * TS + sOff) * 2;

    auto stage = [&](int kt) {
        const unsigned so = (unsigned)(kt % NSTAGE) * (STG_H * 2);
        const __half* ag = aG0 + kt * BK;
        const __half* bg = bG0 + kt * BK;
        cp16(aS0 + so,      ag);
        cp16(aS0 + so + 16, ag + 8);
        cp16(bS0 + so,      bg);
        cp16(bS0 + so + 16, bg + 8);
        asm volatile("cp.async.commit_group;\n");
    };

    // ldmatrix per-lane source addresses (bytes):
    // A x4: row = wm*32 + mi*16 + (lane&15), col halfs = ks*16 + ((lane>>4)<<3)
    // B x4: n   = wn*64 + np*16 + (lane&7) + ((lane>>4)<<3),
    //       col halfs = ks*16 + (((lane>>3)&1)<<3)
    const unsigned aLd = smemB +
        (unsigned)(((wm * 32 + (lane & 15)) * TS + ((lane >> 4) << 3)) * 2);
    const unsigned bLd = smemB +
        (unsigned)((TILE_H + (wn * 64 + (lane & 7) + ((lane >> 4) << 3)) * TS
                    + (((lane >> 3) & 1) << 3)) * 2);

    float acc[2][8][4];
#pragma unroll
    for (int mi = 0; mi < 2; mi++)
#pragma unroll
        for (int ni = 0; ni < 8; ni++)
#pragma unroll
            for (int c = 0; c < 4; c++) acc[mi][ni][c] = 0.f;

    const int T = K >> 5;               // >= 5 for all layers
    stage(0);
    stage(1);
    stage(2);

    for (int kt = 0; kt < T; kt++) {
        // make group kt resident (allow up to 2 newer groups in flight)
        if (kt + 2 < T)      asm volatile("cp.async.wait_group 2;\n" ::: "memory");
        else if (kt + 1 < T) asm volatile("cp.async.wait_group 1;\n" ::: "memory");
        else                 asm volatile("cp.async.wait_group 0;\n" ::: "memory");
        __syncthreads();   // single barrier: publishes buf kt%4 to all warps AND
                           // proves all warps finished reading buf (kt+3)%4
                           // (last consumed at iteration kt-1) before restaging
        if (kt + 3 < T) stage(kt + 3);

        const unsigned so = (unsigned)(kt % NSTAGE) * (STG_H * 2);

#pragma unroll
        for (int ks = 0; ks < 2; ks++) {               // two k16 steps per BK=32
            const unsigned kb = so + (unsigned)(ks * 32);   // 16 halfs = 32 B
            unsigned a[2][4], b[8][2];
            ldsm_x4(a[0][0], a[0][1], a[0][2], a[0][3], aLd + kb);
            ldsm_x4(a[1][0], a[1][1], a[1][2], a[1][3], aLd + kb + 16 * TS * 2);
#pragma unroll
            for (int np = 0; np < 4; np++)
                ldsm_x4(b[2*np][0], b[2*np][1], b[2*np+1][0], b[2*np+1][1],
                        bLd + kb + (unsigned)(np * 16 * TS * 2));
#pragma unroll
            for (int mi = 0; mi < 2; mi++)
#pragma unroll
                for (int ni = 0; ni < 8; ni++)
                    mma_f16(acc[mi][ni], a[mi], b[ni]);
        }
    }

    // epilogue: bias + relu -> fp16 store (half2)
#pragma unroll
    for (int ni = 0; ni < 8; ni++) {
        const int col = blockN + wn * 64 + ni * 8 + 2 * (lane & 3);
        const float bb0 = bias[col];
        const float bb1 = bias[col + 1];
#pragma unroll
        for (int mi = 0; mi < 2; mi++) {
            const int row = blockM + wm * 32 + mi * 16 + (lane >> 2);
            float v0 = fmaxf(acc[mi][ni][0] + bb0, 0.f);
            float v1 = fmaxf(acc[mi][ni][1] + bb1, 0.f);
            float v2 = fmaxf(acc[mi][ni][2] + bb0, 0.f);
            float v3 = fmaxf(acc[mi][ni][3] + bb1, 0.f);
            *(__half2*)&C[(size_t)row * ldc + col]       = __floats2half2_rn(v0, v1);
            *(__half2*)&C[(size_t)(row + 8) * ldc + col] = __floats2half2_rn(v2, v3);
        }
    }
}

// ---------------------------------------------------------------------------
// Head layer 2 + tanh + Gaussian log prob; gathers fp16 Z via slot map.
// ---------------------------------------------------------------------------
__global__ void __launch_bounds__(256)
head2_logprob_kernel(const __half* __restrict__ Z,      // [M2,512] compact fp16
                     const int*   __restrict__ role_ids,
                     const float* __restrict__ actions,
                     const float* __restrict__ hW2,     // [2*512*8]
                     const float* __restrict__ hb2,
                     const float* __restrict__ logstd,
                     float* __restrict__ out)
{
    __shared__ float sW[2 * 8 * 512];  // [r][k][m]
    __shared__ float sb[16];
    __shared__ float sls[16];

    const int tid = threadIdx.x;
    for (int idx = tid; idx < 8192; idx += 256) {
        int r = idx >> 12, rem = idx & 4095, m = rem >> 3, k = rem & 7;
        sW[r * 4096 + k * 512 + m] = hW2[idx];
    }
    if (tid < 16) { sb[tid] = hb2[tid]; sls[tid] = logstd[tid]; }
    __syncthreads();

    const int warp = tid >> 5, lane = tid & 31;
    const int t = blockIdx.x * 8 + warp;

    const int role = role_ids[t];
    if (role >= 2) { if (lane == 0) out[t] = 0.f; return; }
    const int p = g_slot[t];

    const __half2* z2 = (const __half2*)(Z + (size_t)p * 512);
    const float* w = sW + role * 4096;

    float s[8];
#pragma unroll
    for (int k = 0; k < 8; k++) s[k] = 0.f;
#pragma unroll
    for (int j = 0; j < 8; j++) {
        const int i2 = lane + j * 32;            // half2 index, 256 total
        const float2 zf = __half22float2(z2[i2]);
        const int m = i2 * 2;
#pragma unroll
        for (int k = 0; k < 8; k++)
            s[k] += zf.x * w[k * 512 + m] + zf.y * w[k * 512 + m + 1];
    }
#pragma unroll
    for (int k = 0; k < 8; k++)
#pragma unroll
        for (int off = 16; off; off >>= 1)
            s[k] += __shfl_xor_sync(0xffffffffu, s[k], off);

    if (lane == 0) {
        float lp = 0.f;
#pragma unroll
        for (int k = 0; k < 8; k++) {
            float mean = tanhf(s[k] + sb[role * 8 + k]);
            float ls = sls[role * 8 + k];
            float d = (actions[t * 8 + k] - mean) * expf(-ls);
            lp += -0.5f * d * d - ls - 0.91893853320467274178f;
        }
        out[t] = lp;
    }
}

extern "C" void kernel_launch(void* const* d_in, const int* in_sizes, int n_in,
                              void* d_out, int out_size)
{
    const float* obs      = (const float*)d_in[0];
    const int*   role_ids = (const int*)  d_in[1];
    const float* actions  = (const float*)d_in[2];
    const float* W0  = (const float*)d_in[3];
    const float* b0  = (const float*)d_in[4];
    const float* W1  = (const float*)d_in[5];
    const float* b1  = (const float*)d_in[6];
    const float* W2  = (const float*)d_in[7];
    const float* b2  = (const float*)d_in[8];
    const float* hW1 = (const float*)d_in[9];
    const float* hb1 = (const float*)d_in[10];  // [2,512]
    const float* hW2 = (const float*)d_in[11];
    const float* hb2 = (const float*)d_in[12];
    const float* lsd = (const float*)d_in[13];
    float* out = (float*)d_out;

    __half *bufA, *bufB, *xpad, *zb, *wt;
    int *meta;
    cudaGetSymbolAddress((void**)&bufA, g_bufA);
    cudaGetSymbolAddress((void**)&bufB, g_bufB);
    cudaGetSymbolAddress((void**)&xpad, g_xpad);
    cudaGetSymbolAddress((void**)&zb,   g_z);
    cudaGetSymbolAddress((void**)&wt,   g_wt);
    cudaGetSymbolAddress((void**)&meta, g_meta);

    cudaFuncSetAttribute(gemm_f16<0>, cudaFuncAttributeMaxDynamicSharedMemorySize, SMEM_BYTES);
    cudaFuncSetAttribute(gemm_f16<1>, cudaFuncAttributeMaxDynamicSharedMemorySize, SMEM_BYTES);

    // compaction + packs
    count_roles<<<256, 128>>>(role_ids);
    scan_roles<<<1, 256>>>();
    assign_slots<<<256, 128>>>(role_ids);
    pack_x_compact<<<M_TOTAL / 8, 160>>>(obs, role_ids, xpad);
    zero_pads<<<256, 160>>>(xpad);
    transpose_all<<<3232, dim3(32, 8)>>>(W0, W1, W2, hW1, wt);

    const int GY = MMAX / BM;             // 258, blocks early-exit past M2
    dim3 block(256);
    dim3 gridMain(8, GY);                 // N=1024
    dim3 gridHead(4, GY);                 // N=512

    // shared layers on compacted rows [0, M2)
    gemm_f16<0><<<gridMain, block, SMEM_BYTES>>>(xpad, 160,  wt + W0T_OFF, wt + W0T_OFF, 160,  b0, b0, bufA, 1024, 160,  meta);
    gemm_f16<0><<<gridMain, block, SMEM_BYTES>>>(bufA, 1024, wt + W1T_OFF, wt + W1T_OFF, 1024, b1, b1, bufB, 1024, 1024, meta);
    gemm_f16<0><<<gridMain, block, SMEM_BYTES>>>(bufB, 1024, wt + W2T_OFF, wt + W2T_OFF, 1024, b2, b2, bufA, 1024, 1024, meta);
    // head1, single launch: role0 weights below S1, role1 above
    gemm_f16<1><<<gridHead, block, SMEM_BYTES>>>(bufA, 1024,
                                                 wt + HW1T_OFF, wt + HW1T_OFF + 512*1024, 1024,
                                                 hb1, hb1 + 512,
                                                 zb, 512, 1024, meta);
    // head2 + tanh + Gaussian log-prob, gather via slot map
    head2_logprob_kernel<<<M_TOTAL / 8, 256>>>(zb, role_ids, actions,
                                               hW2, hb2, lsd, out);
}

// round 16
// speedup vs baseline: 1.1732x; 1.0391x over previous
#include <cuda_runtime.h>
#include <cuda_fp16.h>
#include <cstdint>
#include <math.h>

// ---------------------------------------------------------------------------
// ActorMultiHead — fp16 mma.sync (m16n8k16, fp32 accum) + role compaction.
// R16: R15 GEMM core frozen (4-stage ring, 1 barrier/k-tile). Overhead cuts:
//      vectorized pack_x with fused pad-row zeroing; head2 at 4 tokens/warp.
//
//   1. compact tokens: role0 -> [0,C0), role1 -> [S1,S1+C1), S1=align128(C0)
//   2. 3 shared layers on M2 rows (~2/3 of tokens), fp16 in / fp32 acc
//   3. head1 ONE launch over [0,M2); per-block weight select at S1 boundary
//   4. head2+logprob gathers via slot map; role2 -> exact 0
// Weights pre-packed fp16 TRANSPOSED [N][K]; activations fp16 [M][K].
// ---------------------------------------------------------------------------

#define M_TOTAL  32768
#define MMAX     (M_TOTAL + 256)
#define BM 128
#define BN 128
#define BK 32
#define TS 40                        // smem row stride in halfs (80B): conflict-free
#define TILE_H (128 * TS)            // 5120 halfs per (A|B) tile
#define STG_H  (2 * TILE_H)          // 10240 halfs per stage
#define NSTAGE 4
#define SMEM_BYTES (NSTAGE * STG_H * 2)   // 81920 B dynamic

// fp16 transposed weight pack offsets (halfs)
#define W0T_OFF  0                               // [1024][160]
#define W1T_OFF  (1024 * 160)
#define W2T_OFF  (W1T_OFF + 1024 * 1024)
#define HW1T_OFF (W2T_OFF + 1024 * 1024)         // [2][512][1024]
#define WT_TOTAL (HW1T_OFF + 2 * 512 * 1024)

// Scratch (allocation-free __device__ globals)
__device__ __half g_bufA[MMAX * 1024];
__device__ __half g_bufB[MMAX * 1024];
__device__ __half g_xpad[MMAX * 160];
__device__ __half g_z[MMAX * 512];
__device__ __half g_wt[WT_TOTAL];
__device__ int   g_slot[M_TOTAL];
__device__ int   g_cnt0[256], g_cnt1[256];
__device__ int   g_base0[256], g_base1[256];
__device__ int   g_meta[8];   // 1:M2  3:S1  6:C0  7:C1

__device__ __forceinline__ void mma_f16(float d[4], const unsigned a[4], const unsigned b[2]) {
    asm("mma.sync.aligned.m16n8k16.row.col.f32.f16.f16.f32 "
        "{%0,%1,%2,%3}, {%4,%5,%6,%7}, {%8,%9}, {%0,%1,%2,%3};\n"
        : "+f"(d[0]), "+f"(d[1]), "+f"(d[2]), "+f"(d[3])
        : "r"(a[0]), "r"(a[1]), "r"(a[2]), "r"(a[3]), "r"(b[0]), "r"(b[1]));
}

__device__ __forceinline__ void cp16(unsigned s, const void* g) {
    asm volatile("cp.async.cg.shared.global [%0], [%1], 16;\n" :: "r"(s), "l"(g));
}

__device__ __forceinline__ void ldsm_x4(unsigned &r0, unsigned &r1, unsigned &r2,
                                        unsigned &r3, unsigned a) {
    asm volatile("ldmatrix.sync.aligned.m8n8.x4.shared.b16 {%0,%1,%2,%3}, [%4];"
                 : "=r"(r0), "=r"(r1), "=r"(r2), "=r"(r3) : "r"(a));
}

// ---------------------------------------------------------------------------
// Compaction: count -> scan (parallel) -> slot assignment
// ---------------------------------------------------------------------------
__global__ void count_roles(const int* __restrict__ roles)
{
    const int blk = blockIdx.x, tid = threadIdx.x;     // 256 x 128
    const int role = roles[blk * 128 + tid];
    const unsigned m0 = __ballot_sync(0xffffffffu, role == 0);
    const unsigned m1 = __ballot_sync(0xffffffffu, role == 1);
    __shared__ int c0[4], c1[4];
    if ((tid & 31) == 0) { c0[tid >> 5] = __popc(m0); c1[tid >> 5] = __popc(m1); }
    __syncthreads();
    if (tid == 0) {
        g_cnt0[blk] = c0[0] + c0[1] + c0[2] + c0[3];
        g_cnt1[blk] = c1[0] + c1[1] + c1[2] + c1[3];
    }
}

__global__ void scan_roles()        // 256 threads, Hillis-Steele
{
    __shared__ int s0[256], s1[256];
    const int tid = threadIdx.x;
    const int my0 = g_cnt0[tid], my1 = g_cnt1[tid];
    s0[tid] = my0; s1[tid] = my1;
    __syncthreads();
    for (int d = 1; d < 256; d <<= 1) {
        int v0 = (tid >= d) ? s0[tid - d] : 0;
        int v1 = (tid >= d) ? s1[tid - d] : 0;
        __syncthreads();
        s0[tid] += v0; s1[tid] += v1;
        __syncthreads();
    }
    const int C0 = s0[255];
    const int S1 = (C0 + 127) & ~127;
    g_base0[tid] = s0[tid] - my0;              // exclusive prefix
    g_base1[tid] = S1 + s1[tid] - my1;
    if (tid == 255) {
        const int C1 = s1[255];
        const int M2 = S1 + ((C1 + 127) & ~127);
        g_meta[0] = 0;  g_meta[1] = M2;
        g_meta[2] = 0;  g_meta[3] = S1;
        g_meta[4] = S1; g_meta[5] = M2;
        g_meta[6] = C0; g_meta[7] = C1;
    }
}

__global__ void assign_slots(const int* __restrict__ roles)
{
    const int blk = blockIdx.x, tid = threadIdx.x;
    const int t = blk * 128 + tid;
    const int role = roles[t];
    const unsigned lt = (1u << (tid & 31)) - 1u;
    const unsigned m0 = __ballot_sync(0xffffffffu, role == 0);
    const unsigned m1 = __ballot_sync(0xffffffffu, role == 1);
    __shared__ int c0[4], c1[4];
    if ((tid & 31) == 0) { c0[tid >> 5] = __popc(m0); c1[tid >> 5] = __popc(m1); }
    __syncthreads();
    int off0 = 0, off1 = 0;
    for (int w = 0; w < (tid >> 5); w++) { off0 += c0[w]; off1 += c1[w]; }
    int slot = -1;
    if (role == 0)      slot = g_base0[blk] + off0 + __popc(m0 & lt);
    else if (role == 1) slot = g_base1[blk] + off1 + __popc(m1 & lt);
    g_slot[t] = slot;
}

// ---------------------------------------------------------------------------
// pack_x: vectorized compact pack + fused pad-row zeroing.
// blocks [0,4096): 8 tokens x 32 lanes; lane does one float4 load + half4 store.
// blocks [4096,4352): zero a padding row (rows from meta).
// ---------------------------------------------------------------------------
__global__ void __launch_bounds__(256)
pack_x_compact(const float* __restrict__ obs,
               const int* __restrict__ roles,
               __half* __restrict__ xp)
{
    const int tid = threadIdx.x;
    if (blockIdx.x >= 4096) {                   // pad-row zeroing
        const int i = blockIdx.x - 4096;
        const int C0 = g_meta[6], C1 = g_meta[7];
        const int S1 = g_meta[3], M2 = g_meta[1];
        const int p0 = S1 - C0;
        int row;
        if (i < p0) row = C0 + i;
        else if (i - p0 < M2 - (S1 + C1)) row = S1 + C1 + (i - p0);
        else return;
        if (tid < 160) xp[row * 160 + tid] = __float2half(0.f);
        return;
    }
    const int j = tid >> 5;                     // token within block (0..7)
    const int l = tid & 31;                     // lane
    const int t = blockIdx.x * 8 + j;
    const int p = g_slot[t];
    if (p < 0) return;

    // cols 4l .. 4l+3 of obs
    const float4 v = *(const float4*)(obs + (size_t)t * 128 + l * 4);
    union { uint2 u; __half h[4]; } pk;
    pk.h[0] = __float2half(v.x); pk.h[1] = __float2half(v.y);
    pk.h[2] = __float2half(v.z); pk.h[3] = __float2half(v.w);
    *(uint2*)(xp + (size_t)p * 160 + l * 4) = pk.u;

    // cols 128..159: one-hot (128,129) + zero pad, lanes 0..7 (4 halfs each)
    if (l < 8) {
        union { uint2 u; __half h[4]; } pz;
        pz.h[0] = pz.h[1] = pz.h[2] = pz.h[3] = __float2half(0.f);
        if (l == 0) {
            const int role = roles[t];
            pz.h[0] = __float2half(role == 0 ? 1.f : 0.f);
            pz.h[1] = __float2half(role == 1 ? 1.f : 0.f);
        }
        *(uint2*)(xp + (size_t)p * 160 + 128 + l * 4) = pz.u;
    }
}

// ---------------------------------------------------------------------------
// Fused weight transpose-pack: dst[n][k] = fp16(src[k][n]), k >= srcK -> 0.
// One launch; blockIdx selects job + tile. grid = 3232 blocks, block (32,8).
// ---------------------------------------------------------------------------
__global__ void transpose_all(const float* __restrict__ W0,
                              const float* __restrict__ W1,
                              const float* __restrict__ W2,
                              const float* __restrict__ hW1,
                              __half* __restrict__ wt)
{
    __shared__ float tile[32][33];
    int bid = blockIdx.x;
    const float* src; int srcK, srcN, dld, kT; __half* dst;
    if (bid < 160)       { src = W0;              srcK = 130;  srcN = 1024; dst = wt + W0T_OFF;              dld = 160;  kT = 5;  }
    else if (bid < 1184) { bid -= 160;  src = W1; srcK = 1024; srcN = 1024; dst = wt + W1T_OFF;              dld = 1024; kT = 32; }
    else if (bid < 2208) { bid -= 1184; src = W2; srcK = 1024; srcN = 1024; dst = wt + W2T_OFF;              dld = 1024; kT = 32; }
    else if (bid < 2720) { bid -= 2208; src = hW1;             srcK = 1024; srcN = 512; dst = wt + HW1T_OFF;             dld = 1024; kT = 32; }
    else                 { bid -= 2720; src = hW1 + 1024*512;  srcK = 1024; srcN = 512; dst = wt + HW1T_OFF + 512*1024; dld = 1024; kT = 32; }
    const int k0 = (bid % kT) * 32, n0 = (bid / kT) * 32;
    for (int i = threadIdx.y; i < 32; i += 8) {
        int k = k0 + i;
        tile[i][threadIdx.x] = (k < srcK) ? src[(size_t)k * srcN + n0 + threadIdx.x] : 0.f;
    }
    __syncthreads();
    for (int i = threadIdx.y; i < 32; i += 8)
        dst[(size_t)(n0 + i) * dld + k0 + threadIdx.x] =
            __float2half(tile[threadIdx.x][i]);
}

// ---------------------------------------------------------------------------
// fp16 GEMM: C[rows,N] = fp16(relu(A @ Bt^T + bias)); rows=[0, meta[1]).
// SPLIT=1: blocks with blockM >= meta[3] use (Bt1, bias1).
// 256 threads, 8 warps (4x2), warp tile 32x64, 4-stage cp.async ring with
// a single __syncthreads per k-tile, ldmatrix.x4 fragment loads.
// ---------------------------------------------------------------------------
template <int SPLIT>
__global__ void __launch_bounds__(256, 2)
gemm_f16(const __half* __restrict__ A, int lda,
         const __half* __restrict__ Bt0, const __half* __restrict__ Bt1, int ldb,
         const float* __restrict__ bias0, const float* __restrict__ bias1,
         __half* __restrict__ C, int ldc, int K,
         const int* __restrict__ meta)
{
    const int blockM = blockIdx.y * BM;
    if (blockM >= meta[1]) return;
    const int blockN = blockIdx.x * BN;

    const __half* Bt = Bt0;
    const float* bias = bias0;
    if (SPLIT && blockM >= meta[3]) { Bt = Bt1; bias = bias1; }

    extern __shared__ __half smem[];     // NSTAGE * STG_H halfs = 81920 B
    const unsigned smemB = (unsigned)__cvta_generic_to_shared(smem);

    const int tid  = threadIdx.x;
    const int lane = tid & 31;
    const int warp = tid >> 5;
    const int wm = warp >> 1;            // 4 warps along M (32 rows each)
    const int wn = warp & 1;             // 2 warps along N (64 cols each)

    // staging: thread handles row tid>>1 of A and of B, 2 x 16B chunks each
    const int sRow = tid >> 1, sOff = (tid & 1) * 16;   // halfs
    const __half* aG0 = A  + (size_t)(blockM + sRow) * lda + sOff;
    const __half* bG0 = Bt + (size_t)(blockN + sRow) * ldb + sOff;
    const unsigned aS0 = smemB + (unsigned)(sRow * TS + sOff) * 2;
    const unsigned bS0 = smemB + (unsigned)(TILE_H + sRow * TS + sOff) * 2;

    auto stage = [&](int kt) {
        const unsigned so = (unsigned)(kt % NSTAGE) * (STG_H * 2);
        const __half* ag = aG0 + kt * BK;
        const __half* bg = bG0 + kt * BK;
        cp16(aS0 + so,      ag);
        cp16(aS0 + so + 16, ag + 8);
        cp16(bS0 + so,      bg);
        cp16(bS0 + so + 16, bg + 8);
        asm volatile("cp.async.commit_group;\n");
    };

    // ldmatrix per-lane source addresses (bytes):
    // A x4: row = wm*32 + mi*16 + (lane&15), col halfs = ks*16 + ((lane>>4)<<3)
    // B x4: n   = wn*64 + np*16 + (lane&7) + ((lane>>4)<<3),
    //       col halfs = ks*16 + (((lane>>3)&1)<<3)
    const unsigned aLd = smemB +
        (unsigned)(((wm * 32 + (lane & 15)) * TS + ((lane >> 4) << 3)) * 2);
    const unsigned bLd = smemB +
        (unsigned)((TILE_H + (wn * 64 + (lane & 7) + ((lane >> 4) << 3)) * TS
                    + (((lane >> 3) & 1) << 3)) * 2);

    float acc[2][8][4];
#pragma unroll
    for (int mi = 0; mi < 2; mi++)
#pragma unroll
        for (int ni = 0; ni < 8; ni++)
#pragma unroll
            for (int c = 0; c < 4; c++) acc[mi][ni][c] = 0.f;

    const int T = K >> 5;               // >= 5 for all layers
    stage(0);
    stage(1);
    stage(2);

    for (int kt = 0; kt < T; kt++) {
        // make group kt resident (allow up to 2 newer groups in flight)
        if (kt + 2 < T)      asm volatile("cp.async.wait_group 2;\n" ::: "memory");
        else if (kt + 1 < T) asm volatile("cp.async.wait_group 1;\n" ::: "memory");
        else                 asm volatile("cp.async.wait_group 0;\n" ::: "memory");
        __syncthreads();   // single barrier: publishes buf kt%4 to all warps AND
                           // proves all warps finished reading buf (kt+3)%4
                           // (last consumed at iteration kt-1) before restaging
        if (kt + 3 < T) stage(kt + 3);

        const unsigned so = (unsigned)(kt % NSTAGE) * (STG_H * 2);

#pragma unroll
        for (int ks = 0; ks < 2; ks++) {               // two k16 steps per BK=32
            const unsigned kb = so + (unsigned)(ks * 32);   // 16 halfs = 32 B
            unsigned a[2][4], b[8][2];
            ldsm_x4(a[0][0], a[0][1], a[0][2], a[0][3], aLd + kb);
            ldsm_x4(a[1][0], a[1][1], a[1][2], a[1][3], aLd + kb + 16 * TS * 2);
#pragma unroll
            for (int np = 0; np < 4; np++)
                ldsm_x4(b[2*np][0], b[2*np][1], b[2*np+1][0], b[2*np+1][1],
                        bLd + kb + (unsigned)(np * 16 * TS * 2));
#pragma unroll
            for (int mi = 0; mi < 2; mi++)
#pragma unroll
                for (int ni = 0; ni < 8; ni++)
                    mma_f16(acc[mi][ni], a[mi], b[ni]);
        }
    }

    // epilogue: bias + relu -> fp16 store (half2)
#pragma unroll
    for (int ni = 0; ni < 8; ni++) {
        const int col = blockN + wn * 64 + ni * 8 + 2 * (lane & 3);
        const float bb0 = bias[col];
        const float bb1 = bias[col + 1];
#pragma unroll
        for (int mi = 0; mi < 2; mi++) {
            const int row = blockM + wm * 32 + mi * 16 + (lane >> 2);
            float v0 = fmaxf(acc[mi][ni][0] + bb0, 0.f);
            float v1 = fmaxf(acc[mi][ni][1] + bb1, 0.f);
            float v2 = fmaxf(acc[mi][ni][2] + bb0, 0.f);
            float v3 = fmaxf(acc[mi][ni][3] + bb1, 0.f);
            *(__half2*)&C[(size_t)row * ldc + col]       = __floats2half2_rn(v0, v1);
            *(__half2*)&C[(size_t)(row + 8) * ldc + col] = __floats2half2_rn(v2, v3);
        }
    }
}

// ---------------------------------------------------------------------------
// Head layer 2 + tanh + Gaussian log prob; 4 tokens per warp (sW reuse).
// ---------------------------------------------------------------------------
__global__ void __launch_bounds__(256)
head2_logprob_kernel(const __half* __restrict__ Z,      // [M2,512] compact fp16
                     const int*   __restrict__ role_ids,
                     const float* __restrict__ actions,
                     const float* __restrict__ hW2,     // [2*512*8]
                     const float* __restrict__ hb2,
                     const float* __restrict__ logstd,
                     float* __restrict__ out)
{
    __shared__ float sW[2 * 8 * 512];  // [r][k][m]
    __shared__ float sb[16];
    __shared__ float sls[16];

    const int tid = threadIdx.x;
    for (int idx = tid; idx < 8192; idx += 256) {
        int r = idx >> 12, rem = idx & 4095, m = rem >> 3, k = rem & 7;
        sW[r * 4096 + k * 512 + m] = hW2[idx];
    }
    if (tid < 16) { sb[tid] = hb2[tid]; sls[tid] = logstd[tid]; }
    __syncthreads();

    const int warp = tid >> 5, lane = tid & 31;

#pragma unroll
    for (int tt = 0; tt < 4; tt++) {
        const int t = blockIdx.x * 32 + warp * 4 + tt;
        const int role = role_ids[t];
        if (role >= 2) { if (lane == 0) out[t] = 0.f; continue; }
        const int p = g_slot[t];

        const __half2* z2 = (const __half2*)(Z + (size_t)p * 512);
        const float* w = sW + role * 4096;

        float s[8];
#pragma unroll
        for (int k = 0; k < 8; k++) s[k] = 0.f;
#pragma unroll
        for (int j = 0; j < 8; j++) {
            const int i2 = lane + j * 32;            // half2 index, 256 total
            const float2 zf = __half22float2(z2[i2]);
            const int m = i2 * 2;
#pragma unroll
            for (int k = 0; k < 8; k++)
                s[k] += zf.x * w[k * 512 + m] + zf.y * w[k * 512 + m + 1];
        }
#pragma unroll
        for (int k = 0; k < 8; k++)
#pragma unroll
            for (int off = 16; off; off >>= 1)
                s[k] += __shfl_xor_sync(0xffffffffu, s[k], off);

        if (lane == 0) {
            float lp = 0.f;
#pragma unroll
            for (int k = 0; k < 8; k++) {
                float mean = tanhf(s[k] + sb[role * 8 + k]);
                float ls = sls[role * 8 + k];
                float d = (actions[t * 8 + k] - mean) * expf(-ls);
                lp += -0.5f * d * d - ls - 0.91893853320467274178f;
            }
            out[t] = lp;
        }
    }
}

extern "C" void kernel_launch(void* const* d_in, const int* in_sizes, int n_in,
                              void* d_out, int out_size)
{
    const float* obs      = (const float*)d_in[0];
    const int*   role_ids = (const int*)  d_in[1];
    const float* actions  = (const float*)d_in[2];
    const float* W0  = (const float*)d_in[3];
    const float* b0  = (const float*)d_in[4];
    const float* W1  = (const float*)d_in[5];
    const float* b1  = (const float*)d_in[6];
    const float* W2  = (const float*)d_in[7];
    const float* b2  = (const float*)d_in[8];
    const float* hW1 = (const float*)d_in[9];
    const float* hb1 = (const float*)d_in[10];  // [2,512]
    const float* hW2 = (const float*)d_in[11];
    const float* hb2 = (const float*)d_in[12];
    const float* lsd = (const float*)d_in[13];
    float* out = (float*)d_out;

    __half *bufA, *bufB, *xpad, *zb, *wt;
    int *meta;
    cudaGetSymbolAddress((void**)&bufA, g_bufA);
    cudaGetSymbolAddress((void**)&bufB, g_bufB);
    cudaGetSymbolAddress((void**)&xpad, g_xpad);
    cudaGetSymbolAddress((void**)&zb,   g_z);
    cudaGetSymbolAddress((void**)&wt,   g_wt);
    cudaGetSymbolAddress((void**)&meta, g_meta);

    cudaFuncSetAttribute(gemm_f16<0>, cudaFuncAttributeMaxDynamicSharedMemorySize, SMEM_BYTES);
    cudaFuncSetAttribute(gemm_f16<1>, cudaFuncAttributeMaxDynamicSharedMemorySize, SMEM_BYTES);

    // compaction + packs
    count_roles<<<256, 128>>>(role_ids);
    scan_roles<<<1, 256>>>();
    assign_slots<<<256, 128>>>(role_ids);
    pack_x_compact<<<4096 + 256, 256>>>(obs, role_ids, xpad);   // pack + pad zero
    transpose_all<<<3232, dim3(32, 8)>>>(W0, W1, W2, hW1, wt);

    const int GY = MMAX / BM;             // 258, blocks early-exit past M2
    dim3 block(256);
    dim3 gridMain(8, GY);                 // N=1024
    dim3 gridHead(4, GY);                 // N=512

    // shared layers on compacted rows [0, M2)
    gemm_f16<0><<<gridMain, block, SMEM_BYTES>>>(xpad, 160,  wt + W0T_OFF, wt + W0T_OFF, 160,  b0, b0, bufA, 1024, 160,  meta);
    gemm_f16<0><<<gridMain, block, SMEM_BYTES>>>(bufA, 1024, wt + W1T_OFF, wt + W1T_OFF, 1024, b1, b1, bufB, 1024, 1024, meta);
    gemm_f16<0><<<gridMain, block, SMEM_BYTES>>>(bufB, 1024, wt + W2T_OFF, wt + W2T_OFF, 1024, b2, b2, bufA, 1024, 1024, meta);
    // head1, single launch: role0 weights below S1, role1 above
    gemm_f16<1><<<gridHead, block, SMEM_BYTES>>>(bufA, 1024,
                                                 wt + HW1T_OFF, wt + HW1T_OFF + 512*1024, 1024,
                                                 hb1, hb1 + 512,
                                                 zb, 512, 1024, meta);
    // head2 + tanh + Gaussian log-prob, 4 tokens/warp, gather via slot map
    head2_logprob_kernel<<<M_TOTAL / 32, 256>>>(zb, role_ids, actions,
                                                hW2, hb2, lsd, out);
}

// round 17
// speedup vs baseline: 1.1735x; 1.0002x over previous
#include <cuda_runtime.h>
#include <cuda_fp16.h>
#include <cstdint>
#include <math.h>

// ---------------------------------------------------------------------------
// ActorMultiHead — fp16 mma.sync (m16n8k16, fp32 accum) + role compaction.
// R17: R16 GEMM core frozen. Launch-count collapse:
//   compact_all (1 kernel, 1 block)  <- count_roles + scan_roles + assign_slots
//   prep_all    (1 kernel)           <- pack_x(+pad zero) + transpose_all
// Slot order within a role segment is arbitrary (GEMMs only need role-segmented
// rows), so a strided single-block compaction is valid and deterministic.
// ---------------------------------------------------------------------------

#define M_TOTAL  32768
#define MMAX     (M_TOTAL + 256)
#define BM 128
#define BN 128
#define BK 32
#define TS 40                        // smem row stride in halfs (80B): conflict-free
#define TILE_H (128 * TS)            // 5120 halfs per (A|B) tile
#define STG_H  (2 * TILE_H)          // 10240 halfs per stage
#define NSTAGE 4
#define SMEM_BYTES (NSTAGE * STG_H * 2)   // 81920 B dynamic

// fp16 transposed weight pack offsets (halfs)
#define W0T_OFF  0                               // [1024][160]
#define W1T_OFF  (1024 * 160)
#define W2T_OFF  (W1T_OFF + 1024 * 1024)
#define HW1T_OFF (W2T_OFF + 1024 * 1024)         // [2][512][1024]
#define WT_TOTAL (HW1T_OFF + 2 * 512 * 1024)

// prep_all grid split
#define PREP_PACK_BLOCKS 4352        // 4096 pack + 256 pad-zero
#define PREP_TRANS_BLOCKS 3232
#define PREP_BLOCKS (PREP_PACK_BLOCKS + PREP_TRANS_BLOCKS)

// Scratch (allocation-free __device__ globals)
__device__ __half g_bufA[MMAX * 1024];
__device__ __half g_bufB[MMAX * 1024];
__device__ __half g_xpad[MMAX * 160];
__device__ __half g_z[MMAX * 512];
__device__ __half g_wt[WT_TOTAL];
__device__ int   g_slot[M_TOTAL];
__device__ int   g_meta[8];   // 1:M2  3:S1  6:C0  7:C1

__device__ __forceinline__ void mma_f16(float d[4], const unsigned a[4], const unsigned b[2]) {
    asm("mma.sync.aligned.m16n8k16.row.col.f32.f16.f16.f32 "
        "{%0,%1,%2,%3}, {%4,%5,%6,%7}, {%8,%9}, {%0,%1,%2,%3};\n"
        : "+f"(d[0]), "+f"(d[1]), "+f"(d[2]), "+f"(d[3])
        : "r"(a[0]), "r"(a[1]), "r"(a[2]), "r"(a[3]), "r"(b[0]), "r"(b[1]));
}

__device__ __forceinline__ void cp16(unsigned s, const void* g) {
    asm volatile("cp.async.cg.shared.global [%0], [%1], 16;\n" :: "r"(s), "l"(g));
}

__device__ __forceinline__ void ldsm_x4(unsigned &r0, unsigned &r1, unsigned &r2,
                                        unsigned &r3, unsigned a) {
    asm volatile("ldmatrix.sync.aligned.m8n8.x4.shared.b16 {%0,%1,%2,%3}, [%4];"
                 : "=r"(r0), "=r"(r1), "=r"(r2), "=r"(r3) : "r"(a));
}

// ---------------------------------------------------------------------------
// compact_all: single block, 1024 threads. Thread i owns tokens t = j*1024+i
// (j=0..31, coalesced). Local counts -> block scan -> slot writes + meta.
// Slot order within each role segment is arbitrary, so this is valid.
// ---------------------------------------------------------------------------
__global__ void __launch_bounds__(1024)
compact_all(const int* __restrict__ roles)
{
    __shared__ int s0[1024], s1[1024];
    const int tid = threadIdx.x;

    int c0 = 0, c1 = 0;
    int myrole[32];
#pragma unroll
    for (int j = 0; j < 32; j++) {
        const int r = roles[j * 1024 + tid];
        myrole[j] = r;
        c0 += (r == 0);
        c1 += (r == 1);
    }
    s0[tid] = c0; s1[tid] = c1;
    __syncthreads();
#pragma unroll
    for (int d = 1; d < 1024; d <<= 1) {
        int v0 = (tid >= d) ? s0[tid - d] : 0;
        int v1 = (tid >= d) ? s1[tid - d] : 0;
        __syncthreads();
        s0[tid] += v0; s1[tid] += v1;
        __syncthreads();
    }
    const int C0 = s0[1023];
    const int C1 = s1[1023];
    const int S1 = (C0 + 127) & ~127;
    const int M2 = S1 + ((C1 + 127) & ~127);
    if (tid == 0) {
        g_meta[0] = 0;  g_meta[1] = M2;
        g_meta[2] = 0;  g_meta[3] = S1;
        g_meta[4] = S1; g_meta[5] = M2;
        g_meta[6] = C0; g_meta[7] = C1;
    }
    int p0 = s0[tid] - c0;          // exclusive prefix
    int p1 = S1 + s1[tid] - c1;
#pragma unroll
    for (int j = 0; j < 32; j++) {
        const int r = myrole[j];
        int slot = -1;
        if (r == 0)      slot = p0++;
        else if (r == 1) slot = p1++;
        g_slot[j * 1024 + tid] = slot;
    }
}

// ---------------------------------------------------------------------------
// prep_all: fused pack_x (+pad-zero) and weight transpose-pack, one launch.
//   blocks [0,4096)            : pack 8 tokens x 32 lanes (float4 -> half4)
//   blocks [4096,4352)         : zero one padding row of xpad
//   blocks [4352, 4352+3232)   : transpose tile job table (flat 256 threads)
// ---------------------------------------------------------------------------
__global__ void __launch_bounds__(256)
prep_all(const float* __restrict__ obs,
         const int* __restrict__ roles,
         __half* __restrict__ xp,
         const float* __restrict__ W0, const float* __restrict__ W1,
         const float* __restrict__ W2, const float* __restrict__ hW1,
         __half* __restrict__ wt)
{
    const int tid = threadIdx.x;

    if (blockIdx.x < 4096) {                    // ---- pack 8 tokens ----
        const int j = tid >> 5;                 // token within block (0..7)
        const int l = tid & 31;                 // lane
        const int t = blockIdx.x * 8 + j;
        const int p = g_slot[t];
        if (p < 0) return;

        const float4 v = *(const float4*)(obs + (size_t)t * 128 + l * 4);
        union { uint2 u; __half h[4]; } pk;
        pk.h[0] = __float2half(v.x); pk.h[1] = __float2half(v.y);
        pk.h[2] = __float2half(v.z); pk.h[3] = __float2half(v.w);
        *(uint2*)(xp + (size_t)p * 160 + l * 4) = pk.u;

        if (l < 8) {
            union { uint2 u; __half h[4]; } pz;
            pz.h[0] = pz.h[1] = pz.h[2] = pz.h[3] = __float2half(0.f);
            if (l == 0) {
                const int role = roles[t];
                pz.h[0] = __float2half(role == 0 ? 1.f : 0.f);
                pz.h[1] = __float2half(role == 1 ? 1.f : 0.f);
            }
            *(uint2*)(xp + (size_t)p * 160 + 128 + l * 4) = pz.u;
        }
        return;
    }

    if (blockIdx.x < PREP_PACK_BLOCKS) {        // ---- pad-row zeroing ----
        const int i = blockIdx.x - 4096;
        const int C0 = g_meta[6], C1 = g_meta[7];
        const int S1 = g_meta[3], M2 = g_meta[1];
        const int p0 = S1 - C0;
        int row;
        if (i < p0) row = C0 + i;
        else if (i - p0 < M2 - (S1 + C1)) row = S1 + C1 + (i - p0);
        else return;
        if (tid < 160) xp[row * 160 + tid] = __float2half(0.f);
        return;
    }

    // ---- weight transpose tile ----
    __shared__ float tile[32][33];
    int bid = blockIdx.x - PREP_PACK_BLOCKS;
    const int tx = tid & 31, ty = tid >> 5;     // (32, 8)
    const float* src; int srcK, srcN, dld, kT; __half* dst;
    if (bid < 160)       { src = W0;              srcK = 130;  srcN = 1024; dst = wt + W0T_OFF;              dld = 160;  kT = 5;  }
    else if (bid < 1184) { bid -= 160;  src = W1; srcK = 1024; srcN = 1024; dst = wt + W1T_OFF;              dld = 1024; kT = 32; }
    else if (bid < 2208) { bid -= 1184; src = W2; srcK = 1024; srcN = 1024; dst = wt + W2T_OFF;              dld = 1024; kT = 32; }
    else if (bid < 2720) { bid -= 2208; src = hW1;             srcK = 1024; srcN = 512; dst = wt + HW1T_OFF;             dld = 1024; kT = 32; }
    else                 { bid -= 2720; src = hW1 + 1024*512;  srcK = 1024; srcN = 512; dst = wt + HW1T_OFF + 512*1024; dld = 1024; kT = 32; }
    const int k0 = (bid % kT) * 32, n0 = (bid / kT) * 32;
    for (int i = ty; i < 32; i += 8) {
        int k = k0 + i;
        tile[i][tx] = (k < srcK) ? src[(size_t)k * srcN + n0 + tx] : 0.f;
    }
    __syncthreads();
    for (int i = ty; i < 32; i += 8)
        dst[(size_t)(n0 + i) * dld + k0 + tx] = __float2half(tile[tx][i]);
}

// ---------------------------------------------------------------------------
// fp16 GEMM: C[rows,N] = fp16(relu(A @ Bt^T + bias)); rows=[0, meta[1]).
// SPLIT=1: blocks with blockM >= meta[3] use (Bt1, bias1).
// 256 threads, 8 warps (4x2), warp tile 32x64, 4-stage cp.async ring with
// a single __syncthreads per k-tile, ldmatrix.x4 fragment loads.
// ---------------------------------------------------------------------------
template <int SPLIT>
__global__ void __launch_bounds__(256, 2)
gemm_f16(const __half* __restrict__ A, int lda,
         const __half* __restrict__ Bt0, const __half* __restrict__ Bt1, int ldb,
         const float* __restrict__ bias0, const float* __restrict__ bias1,
         __half* __restrict__ C, int ldc, int K,
         const int* __restrict__ meta)
{
    const int blockM = blockIdx.y * BM;
    if (blockM >= meta[1]) return;
    const int blockN = blockIdx.x * BN;

    const __half* Bt = Bt0;
    const float* bias = bias0;
    if (SPLIT && blockM >= meta[3]) { Bt = Bt1; bias = bias1; }

    extern __shared__ __half smem[];     // NSTAGE * STG_H halfs = 81920 B
    const unsigned smemB = (unsigned)__cvta_generic_to_shared(smem);

    const int tid  = threadIdx.x;
    const int lane = tid & 31;
    const int warp = tid >> 5;
    const int wm = warp >> 1;            // 4 warps along M (32 rows each)
    const int wn = warp & 1;             // 2 warps along N (64 cols each)

    // staging: thread handles row tid>>1 of A and of B, 2 x 16B chunks each
    const int sRow = tid >> 1, sOff = (tid & 1) * 16;   // halfs
    const __half* aG0 = A  + (size_t)(blockM + sRow) * lda + sOff;
    const __half* bG0 = Bt + (size_t)(blockN + sRow) * ldb + sOff;
    const unsigned aS0 = smemB + (unsigned)(sRow * TS + sOff) * 2;
    const unsigned bS0 = smemB + (unsigned)(TILE_H + sRow * TS + sOff) * 2;

    auto stage = [&](int kt) {
        const unsigned so = (unsigned)(kt % NSTAGE) * (STG_H * 2);
        const __half* ag = aG0 + kt * BK;
        const __half* bg = bG0 + kt * BK;
        cp16(aS0 + so,      ag);
        cp16(aS0 + so + 16, ag + 8);
        cp16(bS0 + so,      bg);
        cp16(bS0 + so + 16, bg + 8);
        asm volatile("cp.async.commit_group;\n");
    };

    // ldmatrix per-lane source addresses (bytes):
    // A x4: row = wm*32 + mi*16 + (lane&15), col halfs = ks*16 + ((lane>>4)<<3)
    // B x4: n   = wn*64 + np*16 + (lane&7) + ((lane>>4)<<3),
    //       col halfs = ks*16 + (((lane>>3)&1)<<3)
    const unsigned aLd = smemB +
        (unsigned)(((wm * 32 + (lane & 15)) * TS + ((lane >> 4) << 3)) * 2);
    const unsigned bLd = smemB +
        (unsigned)((TILE_H + (wn * 64 + (lane & 7) + ((lane >> 4) << 3)) * TS
                    + (((lane >> 3) & 1) << 3)) * 2);

    float acc[2][8][4];
#pragma unroll
    for (int mi = 0; mi < 2; mi++)
#pragma unroll
        for (int ni = 0; ni < 8; ni++)
#pragma unroll
            for (int c = 0; c < 4; c++) acc[mi][ni][c] = 0.f;

    const int T = K >> 5;               // >= 5 for all layers
    stage(0);
    stage(1);
    stage(2);

    for (int kt = 0; kt < T; kt++) {
        // make group kt resident (allow up to 2 newer groups in flight)
        if (kt + 2 < T)      asm volatile("cp.async.wait_group 2;\n" ::: "memory");
        else if (kt + 1 < T) asm volatile("cp.async.wait_group 1;\n" ::: "memory");
        else                 asm volatile("cp.async.wait_group 0;\n" ::: "memory");
        __syncthreads();   // single barrier: publishes buf kt%4 to all warps AND
                           // proves all warps finished reading buf (kt+3)%4
                           // (last consumed at iteration kt-1) before restaging
        if (kt + 3 < T) stage(kt + 3);

        const unsigned so = (unsigned)(kt % NSTAGE) * (STG_H * 2);

#pragma unroll
        for (int ks = 0; ks < 2; ks++) {               // two k16 steps per BK=32
            const unsigned kb = so + (unsigned)(ks * 32);   // 16 halfs = 32 B
            unsigned a[2][4], b[8][2];
            ldsm_x4(a[0][0], a[0][1], a[0][2], a[0][3], aLd + kb);
            ldsm_x4(a[1][0], a[1][1], a[1][2], a[1][3], aLd + kb + 16 * TS * 2);
#pragma unroll
            for (int np = 0; np < 4; np++)
                ldsm_x4(b[2*np][0], b[2*np][1], b[2*np+1][0], b[2*np+1][1],
                        bLd + kb + (unsigned)(np * 16 * TS * 2));
#pragma unroll
            for (int mi = 0; mi < 2; mi++)
#pragma unroll
                for (int ni = 0; ni < 8; ni++)
                    mma_f16(acc[mi][ni], a[mi], b[ni]);
        }
    }

    // epilogue: bias + relu -> fp16 store (half2)
#pragma unroll
    for (int ni = 0; ni < 8; ni++) {
        const int col = blockN + wn * 64 + ni * 8 + 2 * (lane & 3);
        const float bb0 = bias[col];
        const float bb1 = bias[col + 1];
#pragma unroll
        for (int mi = 0; mi < 2; mi++) {
            const int row = blockM + wm * 32 + mi * 16 + (lane >> 2);
            float v0 = fmaxf(acc[mi][ni][0] + bb0, 0.f);
            float v1 = fmaxf(acc[mi][ni][1] + bb1, 0.f);
            float v2 = fmaxf(acc[mi][ni][2] + bb0, 0.f);
            float v3 = fmaxf(acc[mi][ni][3] + bb1, 0.f);
            *(__half2*)&C[(size_t)row * ldc + col]       = __floats2half2_rn(v0, v1);
            *(__half2*)&C[(size_t)(row + 8) * ldc + col] = __floats2half2_rn(v2, v3);
        }
    }
}

// ---------------------------------------------------------------------------
// Head layer 2 + tanh + Gaussian log prob; 4 tokens per warp (sW reuse).
// ---------------------------------------------------------------------------
__global__ void __launch_bounds__(256)
head2_logprob_kernel(const __half* __restrict__ Z,      // [M2,512] compact fp16
                     const int*   __restrict__ role_ids,
                     const float* __restrict__ actions,
                     const float* __restrict__ hW2,     // [2*512*8]
                     const float* __restrict__ hb2,
                     const float* __restrict__ logstd,
                     float* __restrict__ out)
{
    __shared__ float sW[2 * 8 * 512];  // [r][k][m]
    __shared__ float sb[16];
    __shared__ float sls[16];

    const int tid = threadIdx.x;
    for (int idx = tid; idx < 8192; idx += 256) {
        int r = idx >> 12, rem = idx & 4095, m = rem >> 3, k = rem & 7;
        sW[r * 4096 + k * 512 + m] = hW2[idx];
    }
    if (tid < 16) { sb[tid] = hb2[tid]; sls[tid] = logstd[tid]; }
    __syncthreads();

    const int warp = tid >> 5, lane = tid & 31;

#pragma unroll
    for (int tt = 0; tt < 4; tt++) {
        const int t = blockIdx.x * 32 + warp * 4 + tt;
        const int role = role_ids[t];
        if (role >= 2) { if (lane == 0) out[t] = 0.f; continue; }
        const int p = g_slot[t];

        const __half2* z2 = (const __half2*)(Z + (size_t)p * 512);
        const float* w = sW + role * 4096;

        float s[8];
#pragma unroll
        for (int k = 0; k < 8; k++) s[k] = 0.f;
#pragma unroll
        for (int j = 0; j < 8; j++) {
            const int i2 = lane + j * 32;            // half2 index, 256 total
            const float2 zf = __half22float2(z2[i2]);
            const int m = i2 * 2;
#pragma unroll
            for (int k = 0; k < 8; k++)
                s[k] += zf.x * w[k * 512 + m] + zf.y * w[k * 512 + m + 1];
        }
#pragma unroll
        for (int k = 0; k < 8; k++)
#pragma unroll
            for (int off = 16; off; off >>= 1)
                s[k] += __shfl_xor_sync(0xffffffffu, s[k], off);

        if (lane == 0) {
            float lp = 0.f;
#pragma unroll
            for (int k = 0; k < 8; k++) {
                float mean = tanhf(s[k] + sb[role * 8 + k]);
                float ls = sls[role * 8 + k];
                float d = (actions[t * 8 + k] - mean) * expf(-ls);
                lp += -0.5f * d * d - ls - 0.91893853320467274178f;
            }
            out[t] = lp;
        }
    }
}

extern "C" void kernel_launch(void* const* d_in, const int* in_sizes, int n_in,
                              void* d_out, int out_size)
{
    const float* obs      = (const float*)d_in[0];
    const int*   role_ids = (const int*)  d_in[1];
    const float* actions  = (const float*)d_in[2];
    const float* W0  = (const float*)d_in[3];
    const float* b0  = (const float*)d_in[4];
    const float* W1  = (const float*)d_in[5];
    const float* b1  = (const float*)d_in[6];
    const float* W2  = (const float*)d_in[7];
    const float* b2  = (const float*)d_in[8];
    const float* hW1 = (const float*)d_in[9];
    const float* hb1 = (const float*)d_in[10];  // [2,512]
    const float* hW2 = (const float*)d_in[11];
    const float* hb2 = (const float*)d_in[12];
    const float* lsd = (const float*)d_in[13];
    float* out = (float*)d_out;

    __half *bufA, *bufB, *xpad, *zb, *wt;
    int *meta;
    cudaGetSymbolAddress((void**)&bufA, g_bufA);
    cudaGetSymbolAddress((void**)&bufB, g_bufB);
    cudaGetSymbolAddress((void**)&xpad, g_xpad);
    cudaGetSymbolAddress((void**)&zb,   g_z);
    cudaGetSymbolAddress((void**)&wt,   g_wt);
    cudaGetSymbolAddress((void**)&meta, g_meta);

    cudaFuncSetAttribute(gemm_f16<0>, cudaFuncAttributeMaxDynamicSharedMemorySize, SMEM_BYTES);
    cudaFuncSetAttribute(gemm_f16<1>, cudaFuncAttributeMaxDynamicSharedMemorySize, SMEM_BYTES);

    // compaction (1 launch) + fused prep: pack_x/pad-zero + weight transposes
    compact_all<<<1, 1024>>>(role_ids);
    prep_all<<<PREP_BLOCKS, 256>>>(obs, role_ids, xpad, W0, W1, W2, hW1, wt);

    const int GY = MMAX / BM;             // 258, blocks early-exit past M2
    dim3 block(256);
    dim3 gridMain(8, GY);                 // N=1024
    dim3 gridHead(4, GY);                 // N=512

    // shared layers on compacted rows [0, M2)
    gemm_f16<0><<<gridMain, block, SMEM_BYTES>>>(xpad, 160,  wt + W0T_OFF, wt + W0T_OFF, 160,  b0, b0, bufA, 1024, 160,  meta);
    gemm_f16<0><<<gridMain, block, SMEM_BYTES>>>(bufA, 1024, wt + W1T_OFF, wt + W1T_OFF, 1024, b1, b1, bufB, 1024, 1024, meta);
    gemm_f16<0><<<gridMain, block, SMEM_BYTES>>>(bufB, 1024, wt + W2T_OFF, wt + W2T_OFF, 1024, b2, b2, bufA, 1024, 1024, meta);
    // head1, single launch: role0 weights below S1, role1 above
    gemm_f16<1><<<gridHead, block, SMEM_BYTES>>>(bufA, 1024,
                                                 wt + HW1T_OFF, wt + HW1T_OFF + 512*1024, 1024,
                                                 hb1, hb1 + 512,
                                                 zb, 512, 1024, meta);
    // head2 + tanh + Gaussian log-prob, 4 tokens/warp, gather via slot map
    head2_logprob_kernel<<<M_TOTAL / 32, 256>>>(zb, role_ids, actions,
                                                hW2, hb2, lsd, out);
}